// round 1
// baseline (speedup 1.0000x reference)
#include <cuda_runtime.h>

#define N_NODES 50000
#define N_EDGES 640000
#define DIM 128
#define TILE_F 16384  // floats in a 128x128 tile

// ---- scratch (no allocations allowed; __device__ globals are the sanctioned path) ----
__device__ float g_P[(size_t)N_NODES * 256];    // [n] -> x[n]@W_src (0:128) | x[n]@W_dst (128:256)
__device__ float g_agg[(size_t)N_NODES * DIM];  // scatter-sum of edge messages
__device__ int   g_cnt[N_NODES];                // edges per node
__device__ int   g_row[N_EDGES];
__device__ int   g_col[N_EDGES];
__device__ int   g_is32;

// ---------------------------------------------------------------------------
// helpers
// ---------------------------------------------------------------------------
__device__ __forceinline__ void copy_tile(float* dst, const float* __restrict__ src, int tid) {
    const float4* s = (const float4*)src;
    float4* d = (float4*)dst;
#pragma unroll
    for (int l = 0; l < 16; ++l) d[tid + l * 256] = s[tid + l * 256];
}

__device__ __forceinline__ void copy_tile_guard(float* dst, const float* __restrict__ src,
                                                int tid, int validRows) {
    const float4* s = (const float4*)src;
    float4* d = (float4*)dst;
#pragma unroll
    for (int l = 0; l < 16; ++l) {
        int idx = tid + l * 256;
        int row = idx >> 5;
        float4 v = make_float4(0.f, 0.f, 0.f, 0.f);
        if (row < validRows) v = s[idx];
        d[idx] = v;
    }
}

// C(128x128) += A(128x128 smem row-major) * B(128x128 smem row-major)
// 256 threads, thread (ty,tx) owns 8x8 at (ty*8, tx*8).
__device__ __forceinline__ void gemm128(const float* __restrict__ As, const float* __restrict__ Bs,
                                        float acc[8][8], int m0, int n0) {
#pragma unroll 2
    for (int k = 0; k < 128; ++k) {
        float4 b0 = *(const float4*)(Bs + k * 128 + n0);
        float4 b1 = *(const float4*)(Bs + k * 128 + n0 + 4);
        float a[8];
#pragma unroll
        for (int i = 0; i < 8; ++i) a[i] = As[(m0 + i) * 128 + k];
        float b[8] = {b0.x, b0.y, b0.z, b0.w, b1.x, b1.y, b1.z, b1.w};
#pragma unroll
        for (int i = 0; i < 8; ++i)
#pragma unroll
            for (int j = 0; j < 8; ++j)
                acc[i][j] = fmaf(a[i], b[j], acc[i][j]);
    }
}

// ---------------------------------------------------------------------------
// setup kernels
// ---------------------------------------------------------------------------
__global__ void detect_kernel(const void* __restrict__ p) {
    __shared__ int bad;
    if (threadIdx.x == 0) bad = 0;
    __syncthreads();
    const long long* q = (const long long*)p;
    for (int i = threadIdx.x; i < 2048; i += blockDim.x) {
        long long v = q[i];
        if (v < 0 || v >= N_NODES) bad = 1;
    }
    __syncthreads();
    if (threadIdx.x == 0) g_is32 = bad;
}

__global__ void convert_zero_kernel(const void* __restrict__ p) {
    int is32 = g_is32;
    int t = blockIdx.x * blockDim.x + threadIdx.x;
    int stride = gridDim.x * blockDim.x;
    for (int e = t; e < N_EDGES; e += stride) {
        if (is32) {
            const int* q = (const int*)p;
            g_row[e] = q[e];
            g_col[e] = q[N_EDGES + e];
        } else {
            const long long* q = (const long long*)p;
            g_row[e] = (int)q[e];
            g_col[e] = (int)q[N_EDGES + e];
        }
    }
    size_t na = (size_t)N_NODES * DIM;
    for (size_t i = t; i < na; i += stride) g_agg[i] = 0.f;
    for (int i = t; i < N_NODES; i += stride) g_cnt[i] = 0;
}

// ---------------------------------------------------------------------------
// P = x @ [W_src | W_dst]   (W_src = We1 rows 0..127, W_dst = rows 128..255)
// ---------------------------------------------------------------------------
__global__ __launch_bounds__(256, 1) void pkern(const float* __restrict__ x,
                                                const float* __restrict__ We1) {
    extern __shared__ float sm[];
    float* SB0 = sm;
    float* SB1 = sm + TILE_F;
    float* SB2 = sm + 2 * TILE_F;
    int tid = threadIdx.x, tx = tid & 15, ty = tid >> 4;
    int m0 = ty * 8, n0 = tx * 8;
    int nBase = blockIdx.x * 128;
    int valid = min(128, N_NODES - nBase);

    copy_tile(SB0, We1, tid);             // W_src
    copy_tile(SB1, We1 + TILE_F, tid);    // W_dst
    copy_tile_guard(SB2, x + (size_t)nBase * 128, tid, valid);
    __syncthreads();

    float acc[8][8];
#pragma unroll
    for (int i = 0; i < 8; ++i)
#pragma unroll
        for (int j = 0; j < 8; ++j) acc[i][j] = 0.f;
    gemm128(SB2, SB0, acc, m0, n0);
#pragma unroll
    for (int i = 0; i < 8; ++i) {
        int n = nBase + m0 + i;
        if (n < N_NODES) {
            *(float4*)(g_P + (size_t)n * 256 + n0)     = make_float4(acc[i][0], acc[i][1], acc[i][2], acc[i][3]);
            *(float4*)(g_P + (size_t)n * 256 + n0 + 4) = make_float4(acc[i][4], acc[i][5], acc[i][6], acc[i][7]);
        }
    }
#pragma unroll
    for (int i = 0; i < 8; ++i)
#pragma unroll
        for (int j = 0; j < 8; ++j) acc[i][j] = 0.f;
    gemm128(SB2, SB1, acc, m0, n0);
#pragma unroll
    for (int i = 0; i < 8; ++i) {
        int n = nBase + m0 + i;
        if (n < N_NODES) {
            *(float4*)(g_P + (size_t)n * 256 + 128 + n0)     = make_float4(acc[i][0], acc[i][1], acc[i][2], acc[i][3]);
            *(float4*)(g_P + (size_t)n * 256 + 128 + n0 + 4) = make_float4(acc[i][4], acc[i][5], acc[i][6], acc[i][7]);
        }
    }
}

// ---------------------------------------------------------------------------
// edge kernel: T = attr@W_e; h = relu(T + P_src[row] + P_dst[col] + be1);
//              out = h@We2 + be2; write edge_out; scatter-add into agg/cnt
// ---------------------------------------------------------------------------
__global__ __launch_bounds__(256, 1) void ekern(const float* __restrict__ attr,
                                                const float* __restrict__ We1,
                                                const float* __restrict__ be1,
                                                const float* __restrict__ We2,
                                                const float* __restrict__ be2,
                                                float* __restrict__ edge_out) {
    extern __shared__ float sm[];
    __shared__ int rows_s[128], cols_s[128];
    float* SB0 = sm;
    float* SB1 = sm + TILE_F;
    float* SB2 = sm + 2 * TILE_F;
    int tid = threadIdx.x, tx = tid & 15, ty = tid >> 4;
    int m0 = ty * 8, n0 = tx * 8;
    int eBase = blockIdx.x * 128;

    copy_tile(SB0, We1 + 2 * TILE_F, tid);  // W_e
    copy_tile(SB1, We2, tid);
    copy_tile(SB2, attr + (size_t)eBase * 128, tid);
    if (tid < 128) {
        rows_s[tid] = g_row[eBase + tid];
        cols_s[tid] = g_col[eBase + tid];
    }
    __syncthreads();

    float acc[8][8];
#pragma unroll
    for (int i = 0; i < 8; ++i)
#pragma unroll
        for (int j = 0; j < 8; ++j) acc[i][j] = 0.f;
    gemm128(SB2, SB0, acc, m0, n0);

    float bb[8];
#pragma unroll
    for (int j = 0; j < 8; ++j) bb[j] = __ldg(be1 + n0 + j);

#pragma unroll
    for (int i = 0; i < 8; ++i) {
        int r = rows_s[m0 + i];
        int c = cols_s[m0 + i];
        float4 p0 = *(const float4*)(g_P + (size_t)r * 256 + n0);
        float4 p1 = *(const float4*)(g_P + (size_t)r * 256 + n0 + 4);
        float4 q0 = *(const float4*)(g_P + (size_t)c * 256 + 128 + n0);
        float4 q1 = *(const float4*)(g_P + (size_t)c * 256 + 128 + n0 + 4);
        float ps[8] = {p0.x + q0.x, p0.y + q0.y, p0.z + q0.z, p0.w + q0.w,
                       p1.x + q1.x, p1.y + q1.y, p1.z + q1.z, p1.w + q1.w};
#pragma unroll
        for (int j = 0; j < 8; ++j)
            acc[i][j] = fmaxf(acc[i][j] + ps[j] + bb[j], 0.f);
    }
    __syncthreads();
    // stash hidden in SB2 (attr tile no longer needed)
#pragma unroll
    for (int i = 0; i < 8; ++i) {
        *(float4*)(SB2 + (m0 + i) * 128 + n0)     = make_float4(acc[i][0], acc[i][1], acc[i][2], acc[i][3]);
        *(float4*)(SB2 + (m0 + i) * 128 + n0 + 4) = make_float4(acc[i][4], acc[i][5], acc[i][6], acc[i][7]);
    }
    __syncthreads();

    float acc2[8][8];
#pragma unroll
    for (int i = 0; i < 8; ++i)
#pragma unroll
        for (int j = 0; j < 8; ++j) acc2[i][j] = 0.f;
    gemm128(SB2, SB1, acc2, m0, n0);

#pragma unroll
    for (int j = 0; j < 8; ++j) bb[j] = __ldg(be2 + n0 + j);

#pragma unroll
    for (int i = 0; i < 8; ++i) {
        int e = eBase + m0 + i;
        int r = rows_s[m0 + i];
        float v[8];
#pragma unroll
        for (int j = 0; j < 8; ++j) v[j] = acc2[i][j] + bb[j];
        *(float4*)(edge_out + (size_t)e * 128 + n0)     = make_float4(v[0], v[1], v[2], v[3]);
        *(float4*)(edge_out + (size_t)e * 128 + n0 + 4) = make_float4(v[4], v[5], v[6], v[7]);
#pragma unroll
        for (int j = 0; j < 8; ++j)
            atomicAdd(&g_agg[(size_t)r * 128 + n0 + j], v[j]);
    }
    if (tx == 0) {
#pragma unroll
        for (int i = 0; i < 8; ++i) atomicAdd(&g_cnt[rows_s[m0 + i]], 1);
    }
}

// ---------------------------------------------------------------------------
// node kernel: mean = agg/max(cnt,1); h = relu(x@Wn_x + mean@Wn_m + bn1);
//              x_out = h@Wn2 + bn2
// ---------------------------------------------------------------------------
__global__ __launch_bounds__(256, 1) void nkern(const float* __restrict__ x,
                                                const float* __restrict__ Wn1,
                                                const float* __restrict__ bn1,
                                                const float* __restrict__ Wn2,
                                                const float* __restrict__ bn2,
                                                float* __restrict__ x_out) {
    extern __shared__ float sm[];
    __shared__ float scale_s[128];
    float* SB0 = sm;
    float* SB1 = sm + TILE_F;
    float* SB2 = sm + 2 * TILE_F;
    int tid = threadIdx.x, tx = tid & 15, ty = tid >> 4;
    int m0 = ty * 8, n0 = tx * 8;
    int nBase = blockIdx.x * 128;
    int valid = min(128, N_NODES - nBase);

    copy_tile(SB0, Wn1, tid);            // Wn_x (rows 0..127)
    copy_tile(SB1, Wn1 + TILE_F, tid);   // Wn_m (rows 128..255)
    copy_tile_guard(SB2, x + (size_t)nBase * 128, tid, valid);
    if (tid < 128) {
        int n = nBase + tid;
        float c = (n < N_NODES) ? (float)g_cnt[n] : 1.f;
        scale_s[tid] = 1.f / fmaxf(c, 1.f);
    }
    __syncthreads();

    float acc[8][8];
#pragma unroll
    for (int i = 0; i < 8; ++i)
#pragma unroll
        for (int j = 0; j < 8; ++j) acc[i][j] = 0.f;
    gemm128(SB2, SB0, acc, m0, n0);
    __syncthreads();

    // mean tile into SB2
#pragma unroll
    for (int l = 0; l < 16; ++l) {
        int idx = tid + l * 256;
        int row = idx >> 5, c4 = idx & 31;
        int n = nBase + row;
        float4 v = make_float4(0.f, 0.f, 0.f, 0.f);
        if (n < N_NODES) {
            v = *(const float4*)(g_agg + (size_t)n * 128 + c4 * 4);
            float s = scale_s[row];
            v.x *= s; v.y *= s; v.z *= s; v.w *= s;
        }
        ((float4*)SB2)[idx] = v;
    }
    __syncthreads();
    gemm128(SB2, SB1, acc, m0, n0);

    float bb[8];
#pragma unroll
    for (int j = 0; j < 8; ++j) bb[j] = __ldg(bn1 + n0 + j);
#pragma unroll
    for (int i = 0; i < 8; ++i)
#pragma unroll
        for (int j = 0; j < 8; ++j) acc[i][j] = fmaxf(acc[i][j] + bb[j], 0.f);
    __syncthreads();

    // hidden -> SB2, Wn2 -> SB0
#pragma unroll
    for (int i = 0; i < 8; ++i) {
        *(float4*)(SB2 + (m0 + i) * 128 + n0)     = make_float4(acc[i][0], acc[i][1], acc[i][2], acc[i][3]);
        *(float4*)(SB2 + (m0 + i) * 128 + n0 + 4) = make_float4(acc[i][4], acc[i][5], acc[i][6], acc[i][7]);
    }
    copy_tile(SB0, Wn2, tid);
    __syncthreads();

    float acc2[8][8];
#pragma unroll
    for (int i = 0; i < 8; ++i)
#pragma unroll
        for (int j = 0; j < 8; ++j) acc2[i][j] = 0.f;
    gemm128(SB2, SB0, acc2, m0, n0);

#pragma unroll
    for (int j = 0; j < 8; ++j) bb[j] = __ldg(bn2 + n0 + j);
#pragma unroll
    for (int i = 0; i < 8; ++i) {
        int n = nBase + m0 + i;
        if (n < N_NODES) {
            *(float4*)(x_out + (size_t)n * 128 + n0) =
                make_float4(acc2[i][0] + bb[0], acc2[i][1] + bb[1], acc2[i][2] + bb[2], acc2[i][3] + bb[3]);
            *(float4*)(x_out + (size_t)n * 128 + n0 + 4) =
                make_float4(acc2[i][4] + bb[4], acc2[i][5] + bb[5], acc2[i][6] + bb[6], acc2[i][7] + bb[7]);
        }
    }
}

// ---------------------------------------------------------------------------
extern "C" void kernel_launch(void* const* d_in, const int* in_sizes, int n_in,
                              void* d_out, int out_size) {
    const float* x    = (const float*)d_in[0];
    const void*  eidx = d_in[1];
    const float* attr = (const float*)d_in[2];
    const float* We1  = (const float*)d_in[3];
    const float* be1  = (const float*)d_in[4];
    const float* We2  = (const float*)d_in[5];
    const float* be2  = (const float*)d_in[6];
    const float* Wn1  = (const float*)d_in[7];
    const float* bn1  = (const float*)d_in[8];
    const float* Wn2  = (const float*)d_in[9];
    const float* bn2  = (const float*)d_in[10];

    float* out      = (float*)d_out;
    float* x_out    = out;                                   // [N, 128]
    float* edge_out = out + (size_t)N_NODES * 128;           // [E, 128]

    const int SMEM = 3 * TILE_F * 4;  // 196608 B
    cudaFuncSetAttribute(pkern, cudaFuncAttributeMaxDynamicSharedMemorySize, SMEM);
    cudaFuncSetAttribute(ekern, cudaFuncAttributeMaxDynamicSharedMemorySize, SMEM);
    cudaFuncSetAttribute(nkern, cudaFuncAttributeMaxDynamicSharedMemorySize, SMEM);

    detect_kernel<<<1, 256>>>(eidx);
    convert_zero_kernel<<<640, 256>>>(eidx);
    pkern<<<(N_NODES + 127) / 128, 256, SMEM>>>(x, We1);
    ekern<<<N_EDGES / 128, 256, SMEM>>>(attr, We1, be1, We2, be2, edge_out);
    nkern<<<(N_NODES + 127) / 128, 256, SMEM>>>(x, Wn1, bn1, Wn2, bn2, x_out);
}

// round 3
// speedup vs baseline: 1.8071x; 1.8071x over previous
#include <cuda_runtime.h>
#include <cstdint>

#define N_NODES 50000
#define N_EDGES 640000
#define NUM_ETILES (N_EDGES / 128)   // 5000
#define LDA 132                       // fp32 words per A row (conflict-free frags)
#define LDB 136                       // fp32 words per B row
#define A_FLOATS (128 * LDA)          // 16896
#define B_FLOATS (128 * LDB)          // 17408
#define SMEM_BYTES ((A_FLOATS + 2 * B_FLOATS) * 4)  // 206848

// ---- scratch (__device__ globals; no allocations allowed) ----
__device__ float g_P[(size_t)N_NODES * 256];    // x@W_src (0:128) | x@W_dst (128:256)
__device__ float g_agg[(size_t)N_NODES * 128];
__device__ int   g_cnt[N_NODES];
__device__ int   g_row[N_EDGES];
__device__ int   g_col[N_EDGES];
__device__ int   g_is32;

// ---------------------------------------------------------------------------
// tf32 helpers
// ---------------------------------------------------------------------------
__device__ __forceinline__ uint32_t to_tf32(float x) {
    uint32_t r;
    asm("cvt.rna.tf32.f32 %0, %1;" : "=r"(r) : "f"(x));
    return r;
}

// warp-tile GEMM: acc += A[128x128] * B[128x128]
// A smem row-major [m][k] ld=LDA (tf32 bits); B smem [k][n] ld=LDB (tf32 bits)
// 8 warps: wr = wid>>2 (2 rows of 64), wc = wid&3 (4 cols of 32)
__device__ __forceinline__ void mma_tile(const float* __restrict__ As,
                                         const float* __restrict__ Bs,
                                         float (&acc)[4][4][4],
                                         int lane, int wr, int wc) {
    const int g = lane >> 2, tig = lane & 3;
#pragma unroll
    for (int ks = 0; ks < 16; ++ks) {
        const int k0 = ks * 8;
        uint32_t a[4][4];
#pragma unroll
        for (int mi = 0; mi < 4; ++mi) {
            const float* Ap = As + (wr * 64 + mi * 16 + g) * LDA + k0 + tig;
            a[mi][0] = __float_as_uint(Ap[0]);
            a[mi][1] = __float_as_uint(Ap[8 * LDA]);
            a[mi][2] = __float_as_uint(Ap[4]);
            a[mi][3] = __float_as_uint(Ap[8 * LDA + 4]);
        }
        uint32_t b[4][2];
#pragma unroll
        for (int ni = 0; ni < 4; ++ni) {
            const float* Bp = Bs + (k0 + tig) * LDB + wc * 32 + ni * 8 + g;
            b[ni][0] = __float_as_uint(Bp[0]);
            b[ni][1] = __float_as_uint(Bp[4 * LDB]);
        }
#pragma unroll
        for (int mi = 0; mi < 4; ++mi)
#pragma unroll
            for (int ni = 0; ni < 4; ++ni)
                asm volatile(
                    "mma.sync.aligned.m16n8k8.row.col.f32.tf32.tf32.f32 "
                    "{%0,%1,%2,%3}, {%4,%5,%6,%7}, {%8,%9}, {%0,%1,%2,%3};"
                    : "+f"(acc[mi][ni][0]), "+f"(acc[mi][ni][1]),
                      "+f"(acc[mi][ni][2]), "+f"(acc[mi][ni][3])
                    : "r"(a[mi][0]), "r"(a[mi][1]), "r"(a[mi][2]), "r"(a[mi][3]),
                      "r"(b[ni][0]), "r"(b[ni][1]));
    }
}

__device__ __forceinline__ void zero_acc(float (&acc)[4][4][4]) {
#pragma unroll
    for (int i = 0; i < 4; ++i)
#pragma unroll
        for (int j = 0; j < 4; ++j)
#pragma unroll
            for (int q = 0; q < 4; ++q) acc[i][j][q] = 0.f;
}

// B tile [128][128] row-major gmem -> smem [k][n] ld=LDB, tf32 rounded
__device__ __forceinline__ void load_B_tf32(float* Bs, const float* __restrict__ W, int tid) {
    for (int i = tid; i < 4096; i += 256) {
        int k = i >> 5, n4 = (i & 31) << 2;
        float4 v = __ldg((const float4*)(W + k * 128 + n4));
        uint32_t* d = (uint32_t*)(Bs + k * LDB + n4);
        d[0] = to_tf32(v.x); d[1] = to_tf32(v.y); d[2] = to_tf32(v.z); d[3] = to_tf32(v.w);
    }
}

// A tile [rows][128] gmem -> smem [m][k] ld=LDA, tf32, zero-padded rows
__device__ __forceinline__ void load_A_tf32(float* As, const float* __restrict__ X,
                                            int tid, int validRows) {
    for (int i = tid; i < 4096; i += 256) {
        int r = i >> 5, c4 = (i & 31) << 2;
        float4 v = make_float4(0.f, 0.f, 0.f, 0.f);
        if (r < validRows) v = __ldg((const float4*)(X + (size_t)r * 128 + c4));
        uint32_t* d = (uint32_t*)(As + r * LDA + c4);
        d[0] = to_tf32(v.x); d[1] = to_tf32(v.y); d[2] = to_tf32(v.z); d[3] = to_tf32(v.w);
    }
}

// ---------------------------------------------------------------------------
// setup kernels
// ---------------------------------------------------------------------------
__global__ void detect_kernel(const void* __restrict__ p) {
    __shared__ int bad;
    if (threadIdx.x == 0) bad = 0;
    __syncthreads();
    const long long* q = (const long long*)p;
    for (int i = threadIdx.x; i < 2048; i += blockDim.x) {
        long long v = q[i];
        if (v < 0 || v >= N_NODES) bad = 1;
    }
    __syncthreads();
    if (threadIdx.x == 0) g_is32 = bad;
}

__global__ void convert_zero_kernel(const void* __restrict__ p) {
    int is32 = g_is32;
    int t = blockIdx.x * blockDim.x + threadIdx.x;
    int stride = gridDim.x * blockDim.x;
    for (int e = t; e < N_EDGES; e += stride) {
        if (is32) {
            const int* q = (const int*)p;
            g_row[e] = q[e];
            g_col[e] = q[N_EDGES + e];
        } else {
            const long long* q = (const long long*)p;
            g_row[e] = (int)q[e];
            g_col[e] = (int)q[N_EDGES + e];
        }
    }
    size_t na = (size_t)N_NODES * 128;
    for (size_t i = t; i < na; i += stride) g_agg[i] = 0.f;
    for (int i = t; i < N_NODES; i += stride) g_cnt[i] = 0;
}

__global__ void cnt_kern() {
    int e = blockIdx.x * blockDim.x + threadIdx.x;
    if (e < N_EDGES) atomicAdd(&g_cnt[g_row[e]], 1);
}

// ---------------------------------------------------------------------------
// pkern: g_P = x @ [W_src | W_dst]
// ---------------------------------------------------------------------------
__global__ __launch_bounds__(256, 1) void pkern(const float* __restrict__ x,
                                                const float* __restrict__ We1) {
    extern __shared__ float sm[];
    float* A  = sm;
    float* B0 = sm + A_FLOATS;
    float* B1 = B0 + B_FLOATS;
    int tid = threadIdx.x, lane = tid & 31, wid = tid >> 5;
    int wr = wid >> 2, wc = wid & 3;
    int g = lane >> 2, tig = lane & 3;
    int nBase = blockIdx.x * 128;
    int valid = min(128, N_NODES - nBase);

    load_A_tf32(A, x + (size_t)nBase * 128, tid, valid);
    load_B_tf32(B0, We1, tid);                 // W_src rows 0..127
    load_B_tf32(B1, We1 + 128 * 128, tid);     // W_dst rows 128..255
    __syncthreads();

    float acc1[4][4][4], acc2[4][4][4];
    zero_acc(acc1); zero_acc(acc2);
    mma_tile(A, B0, acc1, lane, wr, wc);
    mma_tile(A, B1, acc2, lane, wr, wc);
    __syncthreads();  // A free

    // two passes: stash acc into A (fp32), then coalesced store to g_P
#pragma unroll
    for (int pass = 0; pass < 2; ++pass) {
        float (&acc)[4][4][4] = pass ? acc2 : acc1;
#pragma unroll
        for (int mi = 0; mi < 4; ++mi)
#pragma unroll
            for (int half = 0; half < 2; ++half) {
                int m = wr * 64 + mi * 16 + g + half * 8;
#pragma unroll
                for (int ni = 0; ni < 4; ++ni) {
                    int c = wc * 32 + ni * 8 + 2 * tig;
                    *(float2*)(A + m * LDA + c) =
                        make_float2(acc[mi][ni][half * 2], acc[mi][ni][half * 2 + 1]);
                }
            }
        __syncthreads();
        int row = tid >> 1, hq = (tid & 1) * 16;
        int n = nBase + row;
        if (n < N_NODES) {
            const float* Ar = A + row * LDA + hq * 4;
            float4* dst = (float4*)(g_P + (size_t)n * 256 + pass * 128 + hq * 4);
#pragma unroll
            for (int i = 0; i < 16; ++i) dst[i] = *(const float4*)(Ar + i * 4);
        }
        __syncthreads();
    }
}

// ---------------------------------------------------------------------------
// ekern: persistent; per 128-edge tile:
//   D1 = attr@W_e ; h = relu(D1 + P_src[row] + P_dst[col] + be1)
//   D2 = h@We2 + be2 ; write edge_out ; float4-atomic scatter into g_agg
// ---------------------------------------------------------------------------
__global__ __launch_bounds__(256, 1) void ekern(const float* __restrict__ attr,
                                                const float* __restrict__ We1,
                                                const float* __restrict__ be1,
                                                const float* __restrict__ We2,
                                                const float* __restrict__ be2,
                                                float* __restrict__ edge_out) {
    extern __shared__ float sm[];
    float* A  = sm;
    float* B1 = sm + A_FLOATS;
    float* B2 = B1 + B_FLOATS;
    __shared__ int rows_s[128], cols_s[128];
    __shared__ float be1s[128], be2s[128];

    int tid = threadIdx.x, lane = tid & 31, wid = tid >> 5;
    int wr = wid >> 2, wc = wid & 3;
    int g = lane >> 2, tig = lane & 3;

    load_B_tf32(B1, We1 + 2 * 128 * 128, tid);  // W_e rows 256..383
    load_B_tf32(B2, We2, tid);
    if (tid < 128) { be1s[tid] = be1[tid]; be2s[tid] = be2[tid]; }
    __syncthreads();

    for (int t = blockIdx.x; t < NUM_ETILES; t += gridDim.x) {
        int eBase = t << 7;
        if (tid < 128) {
            rows_s[tid] = g_row[eBase + tid];
            cols_s[tid] = g_col[eBase + tid];
        }
        load_A_tf32(A, attr + (size_t)eBase * 128, tid, 128);
        __syncthreads();

        float acc1[4][4][4];
        zero_acc(acc1);
        mma_tile(A, B1, acc1, lane, wr, wc);
        __syncthreads();  // all warps done reading A

        // epilogue 1: h = relu(D1 + Psrc + Pdst + be1) -> A (tf32)
#pragma unroll
        for (int mi = 0; mi < 4; ++mi)
#pragma unroll
            for (int half = 0; half < 2; ++half) {
                int m = wr * 64 + mi * 16 + g + half * 8;
                int rs = rows_s[m], cd = cols_s[m];
                const float* Ps = g_P + (size_t)rs * 256;
                const float* Pd = g_P + (size_t)cd * 256 + 128;
#pragma unroll
                for (int ni = 0; ni < 4; ++ni) {
                    int c = wc * 32 + ni * 8 + 2 * tig;
                    float2 p = *(const float2*)(Ps + c);
                    float2 q = *(const float2*)(Pd + c);
                    float v0 = fmaxf(acc1[mi][ni][half * 2]     + p.x + q.x + be1s[c],     0.f);
                    float v1 = fmaxf(acc1[mi][ni][half * 2 + 1] + p.y + q.y + be1s[c + 1], 0.f);
                    uint2 w = make_uint2(to_tf32(v0), to_tf32(v1));
                    *(uint2*)(A + m * LDA + c) = w;
                }
            }
        __syncthreads();

        float acc2[4][4][4];
        zero_acc(acc2);
        mma_tile(A, B2, acc2, lane, wr, wc);
        __syncthreads();

        // epilogue 2: stash D2+be2 into A (fp32), then coalesced out + v4 atomics
#pragma unroll
        for (int mi = 0; mi < 4; ++mi)
#pragma unroll
            for (int half = 0; half < 2; ++half) {
                int m = wr * 64 + mi * 16 + g + half * 8;
#pragma unroll
                for (int ni = 0; ni < 4; ++ni) {
                    int c = wc * 32 + ni * 8 + 2 * tig;
                    *(float2*)(A + m * LDA + c) =
                        make_float2(acc2[mi][ni][half * 2]     + be2s[c],
                                    acc2[mi][ni][half * 2 + 1] + be2s[c + 1]);
                }
            }
        __syncthreads();
        {
            int row = tid >> 1, hq = (tid & 1) * 16;
            const float* Ar = A + row * LDA + hq * 4;
            float4* eo = (float4*)(edge_out + (size_t)(eBase + row) * 128 + hq * 4);
            float4* ag = (float4*)(g_agg + (size_t)rows_s[row] * 128 + hq * 4);
#pragma unroll
            for (int i = 0; i < 16; ++i) {
                float4 v = *(const float4*)(Ar + i * 4);
                eo[i] = v;
                atomicAdd(ag + i, v);
            }
        }
        __syncthreads();
    }
}

// ---------------------------------------------------------------------------
// nkern: mean = agg/max(cnt,1); h = relu(x@Wn_x + mean@Wn_m + bn1);
//        x_out = h@Wn2 + bn2
// ---------------------------------------------------------------------------
__global__ __launch_bounds__(256, 1) void nkern(const float* __restrict__ x,
                                                const float* __restrict__ Wn1,
                                                const float* __restrict__ bn1,
                                                const float* __restrict__ Wn2,
                                                const float* __restrict__ bn2,
                                                float* __restrict__ x_out) {
    extern __shared__ float sm[];
    float* A  = sm;
    float* B0 = sm + A_FLOATS;
    float* B1 = B0 + B_FLOATS;
    __shared__ float bn1s[128], bn2s[128], scale_s[128];

    int tid = threadIdx.x, lane = tid & 31, wid = tid >> 5;
    int wr = wid >> 2, wc = wid & 3;
    int g = lane >> 2, tig = lane & 3;
    int nBase = blockIdx.x * 128;
    int valid = min(128, N_NODES - nBase);

    load_A_tf32(A, x + (size_t)nBase * 128, tid, valid);
    load_B_tf32(B0, Wn1, tid);
    load_B_tf32(B1, Wn1 + 128 * 128, tid);
    if (tid < 128) {
        bn1s[tid] = bn1[tid];
        bn2s[tid] = bn2[tid];
        int n = nBase + tid;
        float c = (n < N_NODES) ? (float)g_cnt[n] : 1.f;
        scale_s[tid] = 1.f / fmaxf(c, 1.f);
    }
    __syncthreads();

    float acc[4][4][4];
    zero_acc(acc);
    mma_tile(A, B0, acc, lane, wr, wc);
    __syncthreads();

    // A <- mean tile (tf32)
    for (int i = tid; i < 4096; i += 256) {
        int r = i >> 5, c4 = (i & 31) << 2;
        int n = nBase + r;
        float4 v = make_float4(0.f, 0.f, 0.f, 0.f);
        if (n < N_NODES) {
            v = *(const float4*)(g_agg + (size_t)n * 128 + c4);
            float s = scale_s[r];
            v.x *= s; v.y *= s; v.z *= s; v.w *= s;
        }
        uint32_t* d = (uint32_t*)(A + r * LDA + c4);
        d[0] = to_tf32(v.x); d[1] = to_tf32(v.y); d[2] = to_tf32(v.z); d[3] = to_tf32(v.w);
    }
    __syncthreads();
    mma_tile(A, B1, acc, lane, wr, wc);
    __syncthreads();

    // h = relu(acc + bn1) -> A (tf32); reload B0 <- Wn2
#pragma unroll
    for (int mi = 0; mi < 4; ++mi)
#pragma unroll
        for (int half = 0; half < 2; ++half) {
            int m = wr * 64 + mi * 16 + g + half * 8;
#pragma unroll
            for (int ni = 0; ni < 4; ++ni) {
                int c = wc * 32 + ni * 8 + 2 * tig;
                float v0 = fmaxf(acc[mi][ni][half * 2]     + bn1s[c],     0.f);
                float v1 = fmaxf(acc[mi][ni][half * 2 + 1] + bn1s[c + 1], 0.f);
                *(uint2*)(A + m * LDA + c) = make_uint2(to_tf32(v0), to_tf32(v1));
            }
        }
    load_B_tf32(B0, Wn2, tid);
    __syncthreads();

    float acc2[4][4][4];
    zero_acc(acc2);
    mma_tile(A, B0, acc2, lane, wr, wc);
    __syncthreads();

#pragma unroll
    for (int mi = 0; mi < 4; ++mi)
#pragma unroll
        for (int half = 0; half < 2; ++half) {
            int m = wr * 64 + mi * 16 + g + half * 8;
#pragma unroll
            for (int ni = 0; ni < 4; ++ni) {
                int c = wc * 32 + ni * 8 + 2 * tig;
                *(float2*)(A + m * LDA + c) =
                    make_float2(acc2[mi][ni][half * 2]     + bn2s[c],
                                acc2[mi][ni][half * 2 + 1] + bn2s[c + 1]);
            }
        }
    __syncthreads();
    {
        int row = tid >> 1, hq = (tid & 1) * 16;
        int n = nBase + row;
        if (n < N_NODES) {
            const float* Ar = A + row * LDA + hq * 4;
            float4* dst = (float4*)(x_out + (size_t)n * 128 + hq * 4);
#pragma unroll
            for (int i = 0; i < 16; ++i) dst[i] = *(const float4*)(Ar + i * 4);
        }
    }
}

// ---------------------------------------------------------------------------
extern "C" void kernel_launch(void* const* d_in, const int* in_sizes, int n_in,
                              void* d_out, int out_size) {
    const float* x    = (const float*)d_in[0];
    const void*  eidx = d_in[1];
    const float* attr = (const float*)d_in[2];
    const float* We1  = (const float*)d_in[3];
    const float* be1  = (const float*)d_in[4];
    const float* We2  = (const float*)d_in[5];
    const float* be2  = (const float*)d_in[6];
    const float* Wn1  = (const float*)d_in[7];
    const float* bn1  = (const float*)d_in[8];
    const float* Wn2  = (const float*)d_in[9];
    const float* bn2  = (const float*)d_in[10];

    float* out      = (float*)d_out;
    float* x_out    = out;                          // [N, 128]
    float* edge_out = out + (size_t)N_NODES * 128;  // [E, 128]

    cudaFuncSetAttribute(pkern, cudaFuncAttributeMaxDynamicSharedMemorySize, SMEM_BYTES);
    cudaFuncSetAttribute(ekern, cudaFuncAttributeMaxDynamicSharedMemorySize, SMEM_BYTES);
    cudaFuncSetAttribute(nkern, cudaFuncAttributeMaxDynamicSharedMemorySize, SMEM_BYTES);

    detect_kernel<<<1, 256>>>(eidx);
    convert_zero_kernel<<<640, 256>>>(eidx);
    cnt_kern<<<(N_EDGES + 255) / 256, 256>>>();
    pkern<<<(N_NODES + 127) / 128, 256, SMEM_BYTES>>>(x, We1);
    ekern<<<148, 256, SMEM_BYTES>>>(attr, We1, be1, We2, be2, edge_out);
    nkern<<<(N_NODES + 127) / 128, 256, SMEM_BYTES>>>(x, Wn1, bn1, Wn2, bn2, x_out);
}

// round 4
// speedup vs baseline: 2.4171x; 1.3376x over previous
#include <cuda_runtime.h>
#include <cstdint>

#define N_NODES 50000
#define N_EDGES 640000
#define NUM_ETILES (N_EDGES / 128)   // 5000
#define LDA 132                       // fp32 words per A row (conflict-free frags)
#define LDB 136                       // fp32 words per B row
#define A_FLOATS (128 * LDA)          // 16896
#define B_FLOATS (128 * LDB)          // 17408
#define SMEM_BYTES ((A_FLOATS + 2 * B_FLOATS) * 4)  // 206848

// ---- scratch (__device__ globals; no allocations allowed) ----
__device__ float g_P[(size_t)N_NODES * 256];    // x@W_src (0:128) | x@W_dst (128:256)
__device__ float g_agg[(size_t)N_NODES * 128];
__device__ int   g_cnt[N_NODES];
__device__ int   g_row[N_EDGES];
__device__ int   g_col[N_EDGES];

// ---------------------------------------------------------------------------
// helpers
// ---------------------------------------------------------------------------
__device__ __forceinline__ uint32_t to_tf32(float x) {
    uint32_t r;
    asm("cvt.rna.tf32.f32 %0, %1;" : "=r"(r) : "f"(x));
    return r;
}
__device__ __forceinline__ uint32_t smem_u32(const void* p) {
    uint32_t a;
    asm("{ .reg .u64 t; cvta.to.shared.u64 t, %1; cvt.u32.u64 %0, t; }" : "=r"(a) : "l"(p));
    return a;
}
__device__ __forceinline__ void cp_async16(uint32_t saddr, const void* gsrc, int szbytes) {
    asm volatile("cp.async.ca.shared.global [%0], [%1], 16, %2;"
                 :: "r"(saddr), "l"(gsrc), "r"(szbytes) : "memory");
}
#define CP_COMMIT()   asm volatile("cp.async.commit_group;" ::: "memory")
#define CP_WAIT_ALL() asm volatile("cp.async.wait_group 0;" ::: "memory")

// A tile (raw fp32 rows) via cp.async: 128 rows x 32 float4, 512 threads -> 8 each
__device__ __forceinline__ void cpa_tile(float* As, const float* __restrict__ X,
                                         int tid, int validRows) {
#pragma unroll
    for (int i = 0; i < 8; ++i) {
        int idx = tid + i * 512;
        int r = idx >> 5, c4 = (idx & 31) << 2;
        bool p = r < validRows;
        const float* src = X + (p ? ((size_t)r * 128 + c4) : 0);
        cp_async16(smem_u32(As + r * LDA + c4), src, p ? 16 : 0);
    }
}

// B tile [128][128] row-major gmem -> smem [k][n] ld=LDB, tf32 rounded (once/CTA)
__device__ __forceinline__ void load_B_tf32(float* Bs, const float* __restrict__ W,
                                            int tid, int nthr) {
    for (int i = tid; i < 4096; i += nthr) {
        int k = i >> 5, n4 = (i & 31) << 2;
        float4 v = __ldg((const float4*)(W + k * 128 + n4));
        uint32_t* d = (uint32_t*)(Bs + k * LDB + n4);
        d[0] = to_tf32(v.x); d[1] = to_tf32(v.y); d[2] = to_tf32(v.z); d[3] = to_tf32(v.w);
    }
}

// warp-tile GEMM: acc += A[32-row strip] * B[32-col strip], K=128
// A smem raw fp32 [m][k] ld=LDA (cvt at load); B smem tf32 [k][n] ld=LDB
// 16 warps: warpM = (wid>>2)*32 row base, wc = wid&3 col group of 32
__device__ __forceinline__ void mma_tile32(const float* __restrict__ As,
                                           const float* __restrict__ Bs,
                                           float (&acc)[2][4][4],
                                           int lane, int warpM, int wc) {
    const int g = lane >> 2, tig = lane & 3;
#pragma unroll
    for (int ks = 0; ks < 16; ++ks) {
        const int k0 = ks * 8;
        uint32_t a[2][4];
#pragma unroll
        for (int mi = 0; mi < 2; ++mi) {
            const float* Ap = As + (warpM + mi * 16 + g) * LDA + k0 + tig;
            a[mi][0] = to_tf32(Ap[0]);
            a[mi][1] = to_tf32(Ap[8 * LDA]);
            a[mi][2] = to_tf32(Ap[4]);
            a[mi][3] = to_tf32(Ap[8 * LDA + 4]);
        }
        uint32_t b[4][2];
#pragma unroll
        for (int ni = 0; ni < 4; ++ni) {
            const float* Bp = Bs + (k0 + tig) * LDB + wc * 32 + ni * 8 + g;
            b[ni][0] = __float_as_uint(Bp[0]);
            b[ni][1] = __float_as_uint(Bp[4 * LDB]);
        }
#pragma unroll
        for (int mi = 0; mi < 2; ++mi)
#pragma unroll
            for (int ni = 0; ni < 4; ++ni)
                asm volatile(
                    "mma.sync.aligned.m16n8k8.row.col.f32.tf32.tf32.f32 "
                    "{%0,%1,%2,%3}, {%4,%5,%6,%7}, {%8,%9}, {%0,%1,%2,%3};"
                    : "+f"(acc[mi][ni][0]), "+f"(acc[mi][ni][1]),
                      "+f"(acc[mi][ni][2]), "+f"(acc[mi][ni][3])
                    : "r"(a[mi][0]), "r"(a[mi][1]), "r"(a[mi][2]), "r"(a[mi][3]),
                      "r"(b[ni][0]), "r"(b[ni][1]));
    }
}

__device__ __forceinline__ void zero_acc32(float (&acc)[2][4][4]) {
#pragma unroll
    for (int i = 0; i < 2; ++i)
#pragma unroll
        for (int j = 0; j < 4; ++j)
#pragma unroll
            for (int q = 0; q < 4; ++q) acc[i][j][q] = 0.f;
}

// ---------------------------------------------------------------------------
// setup kernels
// ---------------------------------------------------------------------------
__global__ void zero_kern() {
    int t = blockIdx.x * blockDim.x + threadIdx.x;
    int stride = gridDim.x * blockDim.x;
    float4* a4 = (float4*)g_agg;
    for (int i = t; i < N_NODES * 32; i += stride) a4[i] = make_float4(0.f, 0.f, 0.f, 0.f);
    for (int i = t; i < N_NODES; i += stride) g_cnt[i] = 0;
}

__global__ void conv_kern(const void* __restrict__ p) {
    // per-block dtype detection (int64 declared, int32 possible)
    const long long* q = (const long long*)p;
    int bad = 0;
    for (int i = threadIdx.x; i < 2048; i += blockDim.x) {
        long long v = q[i];
        if (v < 0 || v >= N_NODES) bad = 1;
    }
    int is32 = __syncthreads_or(bad);

    int t = blockIdx.x * blockDim.x + threadIdx.x;
    int stride = gridDim.x * blockDim.x;
    if (is32) {
        const int* qi = (const int*)p;
        for (int e = t; e < N_EDGES; e += stride) {
            int r = qi[e];
            g_row[e] = r;
            g_col[e] = qi[N_EDGES + e];
            atomicAdd(&g_cnt[r], 1);
        }
    } else {
        for (int e = t; e < N_EDGES; e += stride) {
            int r = (int)q[e];
            g_row[e] = r;
            g_col[e] = (int)q[N_EDGES + e];
            atomicAdd(&g_cnt[r], 1);
        }
    }
}

// ---------------------------------------------------------------------------
// pkern: g_P = x @ [W_src | W_dst]
// ---------------------------------------------------------------------------
__global__ __launch_bounds__(512, 1) void pkern(const float* __restrict__ x,
                                                const float* __restrict__ We1) {
    extern __shared__ float sm[];
    float* A  = sm;
    float* B0 = sm + A_FLOATS;
    float* B1 = B0 + B_FLOATS;
    int tid = threadIdx.x, lane = tid & 31, wid = tid >> 5;
    int warpM = (wid >> 2) << 5, wc = wid & 3;
    int g = lane >> 2, tig = lane & 3;
    int nBase = blockIdx.x * 128;
    int valid = min(128, N_NODES - nBase);

    cpa_tile(A, x + (size_t)nBase * 128, tid, valid);
    CP_COMMIT();
    load_B_tf32(B0, We1, tid, 512);                 // W_src
    load_B_tf32(B1, We1 + 128 * 128, tid, 512);     // W_dst
    CP_WAIT_ALL();
    __syncthreads();

    float acc1[2][4][4], acc2[2][4][4];
    zero_acc32(acc1); zero_acc32(acc2);
    mma_tile32(A, B0, acc1, lane, warpM, wc);
    mma_tile32(A, B1, acc2, lane, warpM, wc);
    __syncthreads();  // A free

#pragma unroll
    for (int pass = 0; pass < 2; ++pass) {
        float (&acc)[2][4][4] = pass ? acc2 : acc1;
#pragma unroll
        for (int mi = 0; mi < 2; ++mi)
#pragma unroll
            for (int half = 0; half < 2; ++half) {
                int m = warpM + mi * 16 + g + half * 8;
#pragma unroll
                for (int ni = 0; ni < 4; ++ni) {
                    int c = wc * 32 + ni * 8 + 2 * tig;
                    *(float2*)(A + m * LDA + c) =
                        make_float2(acc[mi][ni][half * 2], acc[mi][ni][half * 2 + 1]);
                }
            }
        __syncthreads();
        int row = tid >> 2;
        int n = nBase + row;
        if (n < N_NODES) {
#pragma unroll
            for (int i = 0; i < 8; ++i) {
                int c = ((tid & 3) + i * 4) << 2;
                *(float4*)(g_P + (size_t)n * 256 + pass * 128 + c) = *(const float4*)(A + row * LDA + c);
            }
        }
        __syncthreads();
    }
}

// ---------------------------------------------------------------------------
// ekern: persistent; per 128-edge tile:
//   D1 = attr@W_e ; h = relu(D1 + P_src[row] + P_dst[col] + be1)
//   D2 = h@We2 + be2 ; coalesced edge_out ; float4-atomic scatter into g_agg
// ---------------------------------------------------------------------------
__global__ __launch_bounds__(512, 1) void ekern(const float* __restrict__ attr,
                                                const float* __restrict__ We1,
                                                const float* __restrict__ be1,
                                                const float* __restrict__ We2,
                                                const float* __restrict__ be2,
                                                float* __restrict__ edge_out) {
    extern __shared__ float sm[];
    float* A  = sm;
    float* B1 = sm + A_FLOATS;
    float* B2 = B1 + B_FLOATS;
    __shared__ int rows_s[128], cols_s[128];
    __shared__ float be1s[128], be2s[128];

    int tid = threadIdx.x, lane = tid & 31, wid = tid >> 5;
    int warpM = (wid >> 2) << 5, wc = wid & 3;
    int g = lane >> 2, tig = lane & 3;

    load_B_tf32(B1, We1 + 2 * 128 * 128, tid, 512);  // W_e
    load_B_tf32(B2, We2, tid, 512);
    if (tid < 128) { be1s[tid] = be1[tid]; be2s[tid] = be2[tid]; }
    __syncthreads();

    for (int t = blockIdx.x; t < NUM_ETILES; t += gridDim.x) {
        int eBase = t << 7;
        cpa_tile(A, attr + (size_t)eBase * 128, tid, 128);
        CP_COMMIT();
        if (tid < 128) {
            rows_s[tid] = g_row[eBase + tid];
            cols_s[tid] = g_col[eBase + tid];
        }
        CP_WAIT_ALL();
        __syncthreads();

        float acc1[2][4][4];
        zero_acc32(acc1);
        mma_tile32(A, B1, acc1, lane, warpM, wc);
        __syncthreads();  // all warps done reading A

        // epilogue 1: h = relu(D1 + Psrc + Pdst + be1) -> A (fp32; cvt at frag load)
#pragma unroll
        for (int mi = 0; mi < 2; ++mi)
#pragma unroll
            for (int half = 0; half < 2; ++half) {
                int m = warpM + mi * 16 + g + half * 8;
                int rs = rows_s[m], cd = cols_s[m];
                const float* Ps = g_P + (size_t)rs * 256;
                const float* Pd = g_P + (size_t)cd * 256 + 128;
#pragma unroll
                for (int ni = 0; ni < 4; ++ni) {
                    int c = wc * 32 + ni * 8 + 2 * tig;
                    float2 p = *(const float2*)(Ps + c);
                    float2 q = *(const float2*)(Pd + c);
                    float v0 = fmaxf(acc1[mi][ni][half * 2]     + p.x + q.x + be1s[c],     0.f);
                    float v1 = fmaxf(acc1[mi][ni][half * 2 + 1] + p.y + q.y + be1s[c + 1], 0.f);
                    *(float2*)(A + m * LDA + c) = make_float2(v0, v1);
                }
            }
        __syncthreads();

        float acc2[2][4][4];
        zero_acc32(acc2);
        mma_tile32(A, B2, acc2, lane, warpM, wc);
        __syncthreads();

        // epilogue 2: stash D2+be2 into A, then coalesced out + float4 atomics
#pragma unroll
        for (int mi = 0; mi < 2; ++mi)
#pragma unroll
            for (int half = 0; half < 2; ++half) {
                int m = warpM + mi * 16 + g + half * 8;
#pragma unroll
                for (int ni = 0; ni < 4; ++ni) {
                    int c = wc * 32 + ni * 8 + 2 * tig;
                    *(float2*)(A + m * LDA + c) =
                        make_float2(acc2[mi][ni][half * 2]     + be2s[c],
                                    acc2[mi][ni][half * 2 + 1] + be2s[c + 1]);
                }
            }
        __syncthreads();
        {
            int row = tid >> 2;
            float* eo = edge_out + (size_t)(eBase + row) * 128;
            float* ag = g_agg + (size_t)rows_s[row] * 128;
#pragma unroll
            for (int i = 0; i < 8; ++i) {
                int c = ((tid & 3) + i * 4) << 2;
                float4 v = *(const float4*)(A + row * LDA + c);
                *(float4*)(eo + c) = v;
                atomicAdd((float4*)(ag + c), v);
            }
        }
        __syncthreads();
    }
}

// ---------------------------------------------------------------------------
// nkern: mean = agg/max(cnt,1); h = relu(x@Wn_x + mean@Wn_m + bn1);
//        x_out = h@Wn2 + bn2
// ---------------------------------------------------------------------------
__global__ __launch_bounds__(512, 1) void nkern(const float* __restrict__ x,
                                                const float* __restrict__ Wn1,
                                                const float* __restrict__ bn1,
                                                const float* __restrict__ Wn2,
                                                const float* __restrict__ bn2,
                                                float* __restrict__ x_out) {
    extern __shared__ float sm[];
    float* A  = sm;
    float* B0 = sm + A_FLOATS;
    float* B1 = B0 + B_FLOATS;
    __shared__ float bn1s[128], bn2s[128], scale_s[128];

    int tid = threadIdx.x, lane = tid & 31, wid = tid >> 5;
    int warpM = (wid >> 2) << 5, wc = wid & 3;
    int g = lane >> 2, tig = lane & 3;
    int nBase = blockIdx.x * 128;
    int valid = min(128, N_NODES - nBase);

    cpa_tile(A, x + (size_t)nBase * 128, tid, valid);
    CP_COMMIT();
    load_B_tf32(B0, Wn1, tid, 512);
    load_B_tf32(B1, Wn1 + 128 * 128, tid, 512);
    if (tid < 128) {
        bn1s[tid] = bn1[tid];
        bn2s[tid] = bn2[tid];
        int n = nBase + tid;
        float c = (n < N_NODES) ? (float)g_cnt[n] : 1.f;
        scale_s[tid] = 1.f / fmaxf(c, 1.f);
    }
    CP_WAIT_ALL();
    __syncthreads();

    float acc[2][4][4];
    zero_acc32(acc);
    mma_tile32(A, B0, acc, lane, warpM, wc);
    __syncthreads();

    // A <- mean tile (fp32; cvt at frag load)
    for (int i = tid; i < 4096; i += 512) {
        int r = i >> 5, c4 = (i & 31) << 2;
        int n = nBase + r;
        float4 v = make_float4(0.f, 0.f, 0.f, 0.f);
        if (n < N_NODES) {
            v = *(const float4*)(g_agg + (size_t)n * 128 + c4);
            float s = scale_s[r];
            v.x *= s; v.y *= s; v.z *= s; v.w *= s;
        }
        *(float4*)(A + r * LDA + c4) = v;
    }
    __syncthreads();
    mma_tile32(A, B1, acc, lane, warpM, wc);
    __syncthreads();

    // h = relu(acc + bn1) -> A; reload B0 <- Wn2
#pragma unroll
    for (int mi = 0; mi < 2; ++mi)
#pragma unroll
        for (int half = 0; half < 2; ++half) {
            int m = warpM + mi * 16 + g + half * 8;
#pragma unroll
            for (int ni = 0; ni < 4; ++ni) {
                int c = wc * 32 + ni * 8 + 2 * tig;
                float v0 = fmaxf(acc[mi][ni][half * 2]     + bn1s[c],     0.f);
                float v1 = fmaxf(acc[mi][ni][half * 2 + 1] + bn1s[c + 1], 0.f);
                *(float2*)(A + m * LDA + c) = make_float2(v0, v1);
            }
        }
    load_B_tf32(B0, Wn2, tid, 512);
    __syncthreads();

    float acc2[2][4][4];
    zero_acc32(acc2);
    mma_tile32(A, B0, acc2, lane, warpM, wc);
    __syncthreads();

#pragma unroll
    for (int mi = 0; mi < 2; ++mi)
#pragma unroll
        for (int half = 0; half < 2; ++half) {
            int m = warpM + mi * 16 + g + half * 8;
#pragma unroll
            for (int ni = 0; ni < 4; ++ni) {
                int c = wc * 32 + ni * 8 + 2 * tig;
                *(float2*)(A + m * LDA + c) =
                    make_float2(acc2[mi][ni][half * 2]     + bn2s[c],
                                acc2[mi][ni][half * 2 + 1] + bn2s[c + 1]);
            }
        }
    __syncthreads();
    {
        int row = tid >> 2;
        int n = nBase + row;
        if (n < N_NODES) {
#pragma unroll
            for (int i = 0; i < 8; ++i) {
                int c = ((tid & 3) + i * 4) << 2;
                *(float4*)(x_out + (size_t)n * 128 + c) = *(const float4*)(A + row * LDA + c);
            }
        }
    }
}

// ---------------------------------------------------------------------------
extern "C" void kernel_launch(void* const* d_in, const int* in_sizes, int n_in,
                              void* d_out, int out_size) {
    const float* x    = (const float*)d_in[0];
    const void*  eidx = d_in[1];
    const float* attr = (const float*)d_in[2];
    const float* We1  = (const float*)d_in[3];
    const float* be1  = (const float*)d_in[4];
    const float* We2  = (const float*)d_in[5];
    const float* be2  = (const float*)d_in[6];
    const float* Wn1  = (const float*)d_in[7];
    const float* bn1  = (const float*)d_in[8];
    const float* Wn2  = (const float*)d_in[9];
    const float* bn2  = (const float*)d_in[10];

    float* out      = (float*)d_out;
    float* x_out    = out;                          // [N, 128]
    float* edge_out = out + (size_t)N_NODES * 128;  // [E, 128]

    cudaFuncSetAttribute(pkern, cudaFuncAttributeMaxDynamicSharedMemorySize, SMEM_BYTES);
    cudaFuncSetAttribute(ekern, cudaFuncAttributeMaxDynamicSharedMemorySize, SMEM_BYTES);
    cudaFuncSetAttribute(nkern, cudaFuncAttributeMaxDynamicSharedMemorySize, SMEM_BYTES);

    zero_kern<<<640, 256>>>();
    conv_kern<<<640, 256>>>(eidx);
    pkern<<<(N_NODES + 127) / 128, 512, SMEM_BYTES>>>(x, We1);
    ekern<<<148, 512, SMEM_BYTES>>>(attr, We1, be1, We2, be2, edge_out);
    nkern<<<(N_NODES + 127) / 128, 512, SMEM_BYTES>>>(x, Wn1, bn1, Wn2, bn2, x_out);
}

// round 6
// speedup vs baseline: 2.4763x; 1.0245x over previous
#include <cuda_runtime.h>
#include <cstdint>

#define N_NODES 50000
#define N_EDGES 640000
#define NUM_ETILES (N_EDGES / 128)   // 5000
#define LDA 132                       // fp32 words per A row (conflict-free frags)
#define LDB 136                       // fp32 words per B row (conflict-free v4 frags)
#define A_FLOATS (128 * LDA)          // 16896
#define B_FLOATS (128 * LDB)          // 17408
#define SMEM_BYTES ((A_FLOATS + 2 * B_FLOATS) * 4)  // 206848

// ---- scratch (__device__ globals; no allocations allowed) ----
__device__ float g_P[(size_t)N_NODES * 256];    // x@W_src (0:128) | x@W_dst (128:256)
__device__ float g_agg[(size_t)N_NODES * 128];
__device__ int   g_cnt[N_NODES];
__device__ int   g_row[N_EDGES];
__device__ int   g_col[N_EDGES];

// ---------------------------------------------------------------------------
// helpers
// ---------------------------------------------------------------------------
__device__ __forceinline__ uint32_t to_tf32(float x) {
    uint32_t r;
    asm("cvt.rna.tf32.f32 %0, %1;" : "=r"(r) : "f"(x));
    return r;
}
__device__ __forceinline__ uint32_t smem_u32(const void* p) {
    uint32_t a;
    asm("{ .reg .u64 t; cvta.to.shared.u64 t, %1; cvt.u32.u64 %0, t; }" : "=r"(a) : "l"(p));
    return a;
}
__device__ __forceinline__ void cp_async16(uint32_t saddr, const void* gsrc, int szbytes) {
    asm volatile("cp.async.ca.shared.global [%0], [%1], 16, %2;"
                 :: "r"(saddr), "l"(gsrc), "r"(szbytes) : "memory");
}
#define CP_COMMIT()   asm volatile("cp.async.commit_group;" ::: "memory")
#define CP_WAIT_ALL() asm volatile("cp.async.wait_group 0;" ::: "memory")

// A tile (raw fp32 rows) via cp.async: 128 rows x 32 float4, 512 threads -> 8 each
__device__ __forceinline__ void cpa_tile(float* As, const float* __restrict__ X,
                                         int tid, int validRows) {
#pragma unroll
    for (int i = 0; i < 8; ++i) {
        int idx = tid + i * 512;
        int r = idx >> 5, c4 = (idx & 31) << 2;
        bool p = r < validRows;
        const float* src = X + (p ? ((size_t)r * 128 + c4) : 0);
        cp_async16(smem_u32(As + r * LDA + c4), src, p ? 16 : 0);
    }
}

// B tile [128][128] row-major gmem -> smem FRAGMENT-MAJOR tf32:
// Bs[k][ (n & ~31) | ((n&7)<<2) | ((n>>3)&3) ] so each warp's 4 ni-values are one float4
__device__ __forceinline__ void load_B_tf32(float* Bs, const float* __restrict__ W,
                                            int tid, int nthr) {
    for (int i = tid; i < 4096; i += nthr) {
        int k = i >> 5, n4 = (i & 31) << 2;
        float4 v = __ldg((const float4*)(W + k * 128 + n4));
        float vals[4] = {v.x, v.y, v.z, v.w};
#pragma unroll
        for (int j = 0; j < 4; ++j) {
            int n = n4 + j;
            int cp = (n & ~31) | ((n & 7) << 2) | ((n >> 3) & 3);
            *(uint32_t*)(Bs + k * LDB + cp) = to_tf32(vals[j]);
        }
    }
}

// warp-tile GEMM: acc += A[32-row strip] * B[32-col strip], K=128
// A smem raw fp32 [m][k] ld=LDA (cvt at load); B smem tf32 fragment-major ld=LDB
// 16 warps: warpM = (wid>>2)*32 row base, wc = wid&3 col group of 32
__device__ __forceinline__ void mma_tile32(const float* __restrict__ As,
                                           const float* __restrict__ Bs,
                                           float (&acc)[2][4][4],
                                           int lane, int warpM, int wc) {
    const int g = lane >> 2, tig = lane & 3;
#pragma unroll
    for (int ks = 0; ks < 16; ++ks) {
        const int k0 = ks * 8;
        uint32_t a[2][4];
#pragma unroll
        for (int mi = 0; mi < 2; ++mi) {
            const float* Ap = As + (warpM + mi * 16 + g) * LDA + k0 + tig;
            a[mi][0] = to_tf32(Ap[0]);
            a[mi][1] = to_tf32(Ap[8 * LDA]);
            a[mi][2] = to_tf32(Ap[4]);
            a[mi][3] = to_tf32(Ap[8 * LDA + 4]);
        }
        float4 b0 = *(const float4*)(Bs + (k0 + tig) * LDB + wc * 32 + (g << 2));
        float4 b1 = *(const float4*)(Bs + (k0 + tig + 4) * LDB + wc * 32 + (g << 2));
        uint32_t bA[4] = {__float_as_uint(b0.x), __float_as_uint(b0.y),
                          __float_as_uint(b0.z), __float_as_uint(b0.w)};
        uint32_t bB[4] = {__float_as_uint(b1.x), __float_as_uint(b1.y),
                          __float_as_uint(b1.z), __float_as_uint(b1.w)};
#pragma unroll
        for (int mi = 0; mi < 2; ++mi)
#pragma unroll
            for (int ni = 0; ni < 4; ++ni)
                asm volatile(
                    "mma.sync.aligned.m16n8k8.row.col.f32.tf32.tf32.f32 "
                    "{%0,%1,%2,%3}, {%4,%5,%6,%7}, {%8,%9}, {%0,%1,%2,%3};"
                    : "+f"(acc[mi][ni][0]), "+f"(acc[mi][ni][1]),
                      "+f"(acc[mi][ni][2]), "+f"(acc[mi][ni][3])
                    : "r"(a[mi][0]), "r"(a[mi][1]), "r"(a[mi][2]), "r"(a[mi][3]),
                      "r"(bA[ni]), "r"(bB[ni]));
    }
}

// dual-B variant: load A fragments once, accumulate into two accs (pkern)
__device__ __forceinline__ void mma_tile32_dual(const float* __restrict__ As,
                                                const float* __restrict__ B0s,
                                                const float* __restrict__ B1s,
                                                float (&acc1)[2][4][4], float (&acc2)[2][4][4],
                                                int lane, int warpM, int wc) {
    const int g = lane >> 2, tig = lane & 3;
#pragma unroll
    for (int ks = 0; ks < 16; ++ks) {
        const int k0 = ks * 8;
        uint32_t a[2][4];
#pragma unroll
        for (int mi = 0; mi < 2; ++mi) {
            const float* Ap = As + (warpM + mi * 16 + g) * LDA + k0 + tig;
            a[mi][0] = to_tf32(Ap[0]);
            a[mi][1] = to_tf32(Ap[8 * LDA]);
            a[mi][2] = to_tf32(Ap[4]);
            a[mi][3] = to_tf32(Ap[8 * LDA + 4]);
        }
#pragma unroll
        for (int which = 0; which < 2; ++which) {
            const float* Bs = which ? B1s : B0s;
            float4 b0 = *(const float4*)(Bs + (k0 + tig) * LDB + wc * 32 + (g << 2));
            float4 b1 = *(const float4*)(Bs + (k0 + tig + 4) * LDB + wc * 32 + (g << 2));
            uint32_t bA[4] = {__float_as_uint(b0.x), __float_as_uint(b0.y),
                              __float_as_uint(b0.z), __float_as_uint(b0.w)};
            uint32_t bB[4] = {__float_as_uint(b1.x), __float_as_uint(b1.y),
                              __float_as_uint(b1.z), __float_as_uint(b1.w)};
            float (&acc)[2][4][4] = which ? acc2 : acc1;
#pragma unroll
            for (int mi = 0; mi < 2; ++mi)
#pragma unroll
                for (int ni = 0; ni < 4; ++ni)
                    asm volatile(
                        "mma.sync.aligned.m16n8k8.row.col.f32.tf32.tf32.f32 "
                        "{%0,%1,%2,%3}, {%4,%5,%6,%7}, {%8,%9}, {%0,%1,%2,%3};"
                        : "+f"(acc[mi][ni][0]), "+f"(acc[mi][ni][1]),
                          "+f"(acc[mi][ni][2]), "+f"(acc[mi][ni][3])
                        : "r"(a[mi][0]), "r"(a[mi][1]), "r"(a[mi][2]), "r"(a[mi][3]),
                          "r"(bA[ni]), "r"(bB[ni]));
        }
    }
}

__device__ __forceinline__ void zero_acc32(float (&acc)[2][4][4]) {
#pragma unroll
    for (int i = 0; i < 2; ++i)
#pragma unroll
        for (int j = 0; j < 4; ++j)
#pragma unroll
            for (int q = 0; q < 4; ++q) acc[i][j][q] = 0.f;
}

// ---------------------------------------------------------------------------
// setup kernels
// ---------------------------------------------------------------------------
__global__ void zero_kern() {
    int t = blockIdx.x * blockDim.x + threadIdx.x;
    int stride = gridDim.x * blockDim.x;
    float4* a4 = (float4*)g_agg;
    for (int i = t; i < N_NODES * 32; i += stride) a4[i] = make_float4(0.f, 0.f, 0.f, 0.f);
    for (int i = t; i < N_NODES; i += stride) g_cnt[i] = 0;
}

__global__ void conv_kern(const void* __restrict__ p) {
    const long long* q = (const long long*)p;
    int bad = 0;
    for (int i = threadIdx.x; i < 2048; i += blockDim.x) {
        long long v = q[i];
        if (v < 0 || v >= N_NODES) bad = 1;
    }
    int is32 = __syncthreads_or(bad);

    int t = blockIdx.x * blockDim.x + threadIdx.x;
    int stride = gridDim.x * blockDim.x;
    if (is32) {
        const int* qi = (const int*)p;
        for (int e = t; e < N_EDGES; e += stride) {
            int r = qi[e];
            g_row[e] = r;
            g_col[e] = qi[N_EDGES + e];
            atomicAdd(&g_cnt[r], 1);
        }
    } else {
        for (int e = t; e < N_EDGES; e += stride) {
            int r = (int)q[e];
            g_row[e] = r;
            g_col[e] = (int)q[N_EDGES + e];
            atomicAdd(&g_cnt[r], 1);
        }
    }
}

// ---------------------------------------------------------------------------
// pkern: g_P = x @ [W_src | W_dst]  (fused dual-B k-loop)
// ---------------------------------------------------------------------------
__global__ __launch_bounds__(512, 1) void pkern(const float* __restrict__ x,
                                                const float* __restrict__ We1) {
    extern __shared__ float sm[];
    float* A  = sm;
    float* B0 = sm + A_FLOATS;
    float* B1 = B0 + B_FLOATS;
    int tid = threadIdx.x, lane = tid & 31, wid = tid >> 5;
    int warpM = (wid >> 2) << 5, wc = wid & 3;
    int g = lane >> 2, tig = lane & 3;
    int nBase = blockIdx.x * 128;
    int valid = min(128, N_NODES - nBase);

    cpa_tile(A, x + (size_t)nBase * 128, tid, valid);
    CP_COMMIT();
    load_B_tf32(B0, We1, tid, 512);                 // W_src
    load_B_tf32(B1, We1 + 128 * 128, tid, 512);     // W_dst
    CP_WAIT_ALL();
    __syncthreads();

    float acc1[2][4][4], acc2[2][4][4];
    zero_acc32(acc1); zero_acc32(acc2);
    mma_tile32_dual(A, B0, B1, acc1, acc2, lane, warpM, wc);
    __syncthreads();  // A free

#pragma unroll
    for (int pass = 0; pass < 2; ++pass) {
        float (&acc)[2][4][4] = pass ? acc2 : acc1;
#pragma unroll
        for (int mi = 0; mi < 2; ++mi)
#pragma unroll
            for (int half = 0; half < 2; ++half) {
                int m = warpM + mi * 16 + g + half * 8;
#pragma unroll
                for (int ni = 0; ni < 4; ++ni) {
                    int c = wc * 32 + ni * 8 + 2 * tig;
                    *(float2*)(A + m * LDA + c) =
                        make_float2(acc[mi][ni][half * 2], acc[mi][ni][half * 2 + 1]);
                }
            }
        __syncthreads();
        int row = tid >> 2;
        int n = nBase + row;
        if (n < N_NODES) {
#pragma unroll
            for (int i = 0; i < 8; ++i) {
                int c = ((tid & 3) + i * 4) << 2;
                *(float4*)(g_P + (size_t)n * 256 + pass * 128 + c) = *(const float4*)(A + row * LDA + c);
            }
        }
        __syncthreads();
    }
}

// ---------------------------------------------------------------------------
// ekern: persistent, software-pipelined:
//   prefetch(t+1) overlaps store/atomics(t); P-gather prefetched under GEMM1
// ---------------------------------------------------------------------------
__global__ __launch_bounds__(512, 1) void ekern(const float* __restrict__ attr,
                                                const float* __restrict__ We1,
                                                const float* __restrict__ be1,
                                                const float* __restrict__ We2,
                                                const float* __restrict__ be2,
                                                float* __restrict__ edge_out) {
    extern __shared__ float sm[];
    float* A  = sm;
    float* B1 = sm + A_FLOATS;
    float* B2 = B1 + B_FLOATS;
    __shared__ int rows_s[2][128], cols_s[2][128];
    __shared__ float be1s[128], be2s[128];

    int tid = threadIdx.x, lane = tid & 31, wid = tid >> 5;
    int warpM = (wid >> 2) << 5, wc = wid & 3;
    int g = lane >> 2, tig = lane & 3;
    const int cbase = wc * 32 + 2 * tig;

    load_B_tf32(B1, We1 + 2 * 128 * 128, tid, 512);  // W_e
    load_B_tf32(B2, We2, tid, 512);
    if (tid < 128) { be1s[tid] = be1[tid]; be2s[tid] = be2[tid]; }

    // prologue: prefetch first tile (all CTAs have blockIdx.x < NUM_ETILES)
    {
        int t0 = blockIdx.x, eB = t0 << 7;
        cpa_tile(A, attr + (size_t)eB * 128, tid, 128);
        if (tid < 32)
            cp_async16(smem_u32(&rows_s[0][tid * 4]), g_row + eB + tid * 4, 16);
        else if (tid < 64)
            cp_async16(smem_u32(&cols_s[0][(tid - 32) * 4]), g_col + eB + (tid - 32) * 4, 16);
        CP_COMMIT();
    }

    int buf = 0;
    for (int t = blockIdx.x; t < NUM_ETILES; t += gridDim.x) {
        int eBase = t << 7;
        CP_WAIT_ALL();
        __syncthreads();   // A + indices visible to all

        // ---- P prefetch for mi=0 rows (hidden under GEMM1) ----
        int m0 = warpM + g, m1 = warpM + 8 + g;
        int r0 = rows_s[buf][m0], c0 = cols_s[buf][m0];
        int r1 = rows_s[buf][m1], c1 = cols_s[buf][m1];
        float2 ps0[2][4], pd0[2][4];
#pragma unroll
        for (int ni = 0; ni < 4; ++ni) {
            int c = cbase + ni * 8;
            ps0[0][ni] = *(const float2*)(g_P + (size_t)r0 * 256 + c);
            pd0[0][ni] = *(const float2*)(g_P + (size_t)c0 * 256 + 128 + c);
            ps0[1][ni] = *(const float2*)(g_P + (size_t)r1 * 256 + c);
            pd0[1][ni] = *(const float2*)(g_P + (size_t)c1 * 256 + 128 + c);
        }

        float acc1[2][4][4];
        zero_acc32(acc1);
        mma_tile32(A, B1, acc1, lane, warpM, wc);
        __syncthreads();  // all warps done reading A

        // ---- epilogue 1: h = relu(D1 + Psrc + Pdst + be1) -> A ----
        {
            // issue mi=1 P loads first (overlap with mi=0 math)
            int m2 = warpM + 16 + g, m3 = warpM + 24 + g;
            int r2 = rows_s[buf][m2], c2 = cols_s[buf][m2];
            int r3 = rows_s[buf][m3], c3 = cols_s[buf][m3];
            float2 ps1[2][4], pd1[2][4];
#pragma unroll
            for (int ni = 0; ni < 4; ++ni) {
                int c = cbase + ni * 8;
                ps1[0][ni] = *(const float2*)(g_P + (size_t)r2 * 256 + c);
                pd1[0][ni] = *(const float2*)(g_P + (size_t)c2 * 256 + 128 + c);
                ps1[1][ni] = *(const float2*)(g_P + (size_t)r3 * 256 + c);
                pd1[1][ni] = *(const float2*)(g_P + (size_t)c3 * 256 + 128 + c);
            }
#pragma unroll
            for (int half = 0; half < 2; ++half) {
                int m = warpM + g + half * 8;
#pragma unroll
                for (int ni = 0; ni < 4; ++ni) {
                    int c = cbase + ni * 8;
                    float v0 = fmaxf(acc1[0][ni][half * 2]     + ps0[half][ni].x + pd0[half][ni].x + be1s[c],     0.f);
                    float v1 = fmaxf(acc1[0][ni][half * 2 + 1] + ps0[half][ni].y + pd0[half][ni].y + be1s[c + 1], 0.f);
                    *(float2*)(A + m * LDA + c) = make_float2(v0, v1);
                }
            }
#pragma unroll
            for (int half = 0; half < 2; ++half) {
                int m = warpM + 16 + g + half * 8;
#pragma unroll
                for (int ni = 0; ni < 4; ++ni) {
                    int c = cbase + ni * 8;
                    float v0 = fmaxf(acc1[1][ni][half * 2]     + ps1[half][ni].x + pd1[half][ni].x + be1s[c],     0.f);
                    float v1 = fmaxf(acc1[1][ni][half * 2 + 1] + ps1[half][ni].y + pd1[half][ni].y + be1s[c + 1], 0.f);
                    *(float2*)(A + m * LDA + c) = make_float2(v0, v1);
                }
            }
        }
        __syncthreads();

        float acc2[2][4][4];
        zero_acc32(acc2);
        mma_tile32(A, B2, acc2, lane, warpM, wc);
        __syncthreads();  // before staging overwrites A

        // ---- stage D2 + be2 into A ----
#pragma unroll
        for (int mi = 0; mi < 2; ++mi)
#pragma unroll
            for (int half = 0; half < 2; ++half) {
                int m = warpM + mi * 16 + g + half * 8;
#pragma unroll
                for (int ni = 0; ni < 4; ++ni) {
                    int c = cbase + ni * 8;
                    *(float2*)(A + m * LDA + c) =
                        make_float2(acc2[mi][ni][half * 2]     + be2s[c],
                                    acc2[mi][ni][half * 2 + 1] + be2s[c + 1]);
                }
            }
        __syncthreads();

        // ---- read staged rows into regs ----
        int row = tid >> 2;
        int rdst = rows_s[buf][row];
        float4 v[8];
#pragma unroll
        for (int i = 0; i < 8; ++i) {
            int c = ((tid & 3) + i * 4) << 2;
            v[i] = *(const float4*)(A + row * LDA + c);
        }
        __syncthreads();  // all staged reads done -> A reusable

        // ---- prefetch next tile into A (overlaps stores/atomics below) ----
        int tn = t + gridDim.x;
        if (tn < NUM_ETILES) {
            int eN = tn << 7;
            cpa_tile(A, attr + (size_t)eN * 128, tid, 128);
            if (tid < 32)
                cp_async16(smem_u32(&rows_s[buf ^ 1][tid * 4]), g_row + eN + tid * 4, 16);
            else if (tid < 64)
                cp_async16(smem_u32(&cols_s[buf ^ 1][(tid - 32) * 4]), g_col + eN + (tid - 32) * 4, 16);
        }
        CP_COMMIT();

        // ---- stores + atomics ----
        {
            float* eo = edge_out + (size_t)(eBase + row) * 128;
            float* ag = g_agg + (size_t)rdst * 128;
#pragma unroll
            for (int i = 0; i < 8; ++i) {
                int c = ((tid & 3) + i * 4) << 2;
                *(float4*)(eo + c) = v[i];
                atomicAdd((float4*)(ag + c), v[i]);
            }
        }
        buf ^= 1;
    }
}

// ---------------------------------------------------------------------------
// nkern: mean = agg/max(cnt,1); h = relu(x@Wn_x + mean@Wn_m + bn1);
//        x_out = h@Wn2 + bn2
// ---------------------------------------------------------------------------
__global__ __launch_bounds__(512, 1) void nkern(const float* __restrict__ x,
                                                const float* __restrict__ Wn1,
                                                const float* __restrict__ bn1,
                                                const float* __restrict__ Wn2,
                                                const float* __restrict__ bn2,
                                                float* __restrict__ x_out) {
    extern __shared__ float sm[];
    float* A  = sm;
    float* B0 = sm + A_FLOATS;
    float* B1 = B0 + B_FLOATS;
    __shared__ float bn1s[128], bn2s[128], scale_s[128];

    int tid = threadIdx.x, lane = tid & 31, wid = tid >> 5;
    int warpM = (wid >> 2) << 5, wc = wid & 3;
    int g = lane >> 2, tig = lane & 3;
    int nBase = blockIdx.x * 128;
    int valid = min(128, N_NODES - nBase);

    cpa_tile(A, x + (size_t)nBase * 128, tid, valid);
    CP_COMMIT();
    load_B_tf32(B0, Wn1, tid, 512);
    load_B_tf32(B1, Wn1 + 128 * 128, tid, 512);
    if (tid < 128) {
        bn1s[tid] = bn1[tid];
        bn2s[tid] = bn2[tid];
        int n = nBase + tid;
        float c = (n < N_NODES) ? (float)g_cnt[n] : 1.f;
        scale_s[tid] = 1.f / fmaxf(c, 1.f);
    }
    CP_WAIT_ALL();
    __syncthreads();

    float acc[2][4][4];
    zero_acc32(acc);
    mma_tile32(A, B0, acc, lane, warpM, wc);
    __syncthreads();

    // A <- mean tile
    for (int i = tid; i < 4096; i += 512) {
        int r = i >> 5, c4 = (i & 31) << 2;
        int n = nBase + r;
        float4 v = make_float4(0.f, 0.f, 0.f, 0.f);
        if (n < N_NODES) {
            v = *(const float4*)(g_agg + (size_t)n * 128 + c4);
            float s = scale_s[r];
            v.x *= s; v.y *= s; v.z *= s; v.w *= s;
        }
        *(float4*)(A + r * LDA + c4) = v;
    }
    __syncthreads();
    mma_tile32(A, B1, acc, lane, warpM, wc);
    __syncthreads();

    // h = relu(acc + bn1) -> A; reload B0 <- Wn2
#pragma unroll
    for (int mi = 0; mi < 2; ++mi)
#pragma unroll
        for (int half = 0; half < 2; ++half) {
            int m = warpM + mi * 16 + g + half * 8;
#pragma unroll
            for (int ni = 0; ni < 4; ++ni) {
                int c = wc * 32 + ni * 8 + 2 * tig;
                float v0 = fmaxf(acc[mi][ni][half * 2]     + bn1s[c],     0.f);
                float v1 = fmaxf(acc[mi][ni][half * 2 + 1] + bn1s[c + 1], 0.f);
                *(float2*)(A + m * LDA + c) = make_float2(v0, v1);
            }
        }
    load_B_tf32(B0, Wn2, tid, 512);
    __syncthreads();

    float acc2[2][4][4];
    zero_acc32(acc2);
    mma_tile32(A, B0, acc2, lane, warpM, wc);
    __syncthreads();

#pragma unroll
    for (int mi = 0; mi < 2; ++mi)
#pragma unroll
        for (int half = 0; half < 2; ++half) {
            int m = warpM + mi * 16 + g + half * 8;
#pragma unroll
            for (int ni = 0; ni < 4; ++ni) {
                int c = wc * 32 + ni * 8 + 2 * tig;
                *(float2*)(A + m * LDA + c) =
                    make_float2(acc2[mi][ni][half * 2]     + bn2s[c],
                                acc2[mi][ni][half * 2 + 1] + bn2s[c + 1]);
            }
        }
    __syncthreads();
    {
        int row = tid >> 2;
        int n = nBase + row;
        if (n < N_NODES) {
#pragma unroll
            for (int i = 0; i < 8; ++i) {
                int c = ((tid & 3) + i * 4) << 2;
                *(float4*)(x_out + (size_t)n * 128 + c) = *(const float4*)(A + row * LDA + c);
            }
        }
    }
}

// ---------------------------------------------------------------------------
extern "C" void kernel_launch(void* const* d_in, const int* in_sizes, int n_in,
                              void* d_out, int out_size) {
    const float* x    = (const float*)d_in[0];
    const void*  eidx = d_in[1];
    const float* attr = (const float*)d_in[2];
    const float* We1  = (const float*)d_in[3];
    const float* be1  = (const float*)d_in[4];
    const float* We2  = (const float*)d_in[5];
    const float* be2  = (const float*)d_in[6];
    const float* Wn1  = (const float*)d_in[7];
    const float* bn1  = (const float*)d_in[8];
    const float* Wn2  = (const float*)d_in[9];
    const float* bn2  = (const float*)d_in[10];

    float* out      = (float*)d_out;
    float* x_out    = out;                          // [N, 128]
    float* edge_out = out + (size_t)N_NODES * 128;  // [E, 128]

    cudaFuncSetAttribute(pkern, cudaFuncAttributeMaxDynamicSharedMemorySize, SMEM_BYTES);
    cudaFuncSetAttribute(ekern, cudaFuncAttributeMaxDynamicSharedMemorySize, SMEM_BYTES);
    cudaFuncSetAttribute(nkern, cudaFuncAttributeMaxDynamicSharedMemorySize, SMEM_BYTES);

    zero_kern<<<640, 256>>>();
    conv_kern<<<640, 256>>>(eidx);
    pkern<<<(N_NODES + 127) / 128, 512, SMEM_BYTES>>>(x, We1);
    ekern<<<148, 512, SMEM_BYTES>>>(attr, We1, be1, We2, be2, edge_out);
    nkern<<<(N_NODES + 127) / 128, 512, SMEM_BYTES>>>(x, Wn1, bn1, Wn2, bn2, x_out);
}

// round 8
// speedup vs baseline: 2.6605x; 1.0744x over previous
#include <cuda_runtime.h>
#include <cstdint>

#define N_NODES 50000
#define N_EDGES 640000
#define LDA 132                       // fp32 words per A row (conflict-free frags)
#define LDB 136                       // fp32 words per B row (conflict-free v4 frags)
#define A_FLOATS (128 * LDA)          // 16896
#define B_FLOATS (128 * LDB)          // 17408
#define SMEM_BYTES ((A_FLOATS + 2 * B_FLOATS) * 4)  // 206848

// ---- scratch (__device__ globals; no allocations allowed) ----
__device__ float g_P[(size_t)N_NODES * 256];    // x@W_src (0:128) | x@W_dst (128:256)
__device__ float g_agg[(size_t)N_NODES * 128];
__device__ int   g_cnt[N_NODES];
__device__ int   g_row[N_EDGES];
__device__ int   g_col[N_EDGES];

// ---------------------------------------------------------------------------
// helpers
// ---------------------------------------------------------------------------
__device__ __forceinline__ uint32_t to_tf32(float x) {
    uint32_t r;
    asm("cvt.rna.tf32.f32 %0, %1;" : "=r"(r) : "f"(x));
    return r;
}
__device__ __forceinline__ uint32_t smem_u32(const void* p) {
    uint32_t a;
    asm("{ .reg .u64 t; cvta.to.shared.u64 t, %1; cvt.u32.u64 %0, t; }" : "=r"(a) : "l"(p));
    return a;
}
__device__ __forceinline__ void cp_async16(uint32_t saddr, const void* gsrc, int szbytes) {
    asm volatile("cp.async.ca.shared.global [%0], [%1], 16, %2;"
                 :: "r"(saddr), "l"(gsrc), "r"(szbytes) : "memory");
}
#define CP_COMMIT()   asm volatile("cp.async.commit_group;" ::: "memory")
#define CP_WAIT_ALL() asm volatile("cp.async.wait_group 0;" ::: "memory")
#define GBAR(id) asm volatile("bar.sync %0, 256;" :: "r"((id) + 1) : "memory")

// A tile (raw fp32 rows) via cp.async: 128 rows x 32 float4, 512 threads -> 8 each
__device__ __forceinline__ void cpa_tile(float* As, const float* __restrict__ X,
                                         int tid, int validRows) {
#pragma unroll
    for (int i = 0; i < 8; ++i) {
        int idx = tid + i * 512;
        int r = idx >> 5, c4 = (idx & 31) << 2;
        bool p = r < validRows;
        const float* src = X + (p ? ((size_t)r * 128 + c4) : 0);
        cp_async16(smem_u32(As + r * LDA + c4), src, p ? 16 : 0);
    }
}

// B tile [128][128] row-major gmem -> smem FRAGMENT-MAJOR tf32:
// Bs[k][ (n & ~31) | ((n&7)<<2) | ((n>>3)&3) ] so each warp's 4 ni-values are one float4
__device__ __forceinline__ void load_B_tf32(float* Bs, const float* __restrict__ W,
                                            int tid, int nthr) {
    for (int i = tid; i < 4096; i += nthr) {
        int k = i >> 5, n4 = (i & 31) << 2;
        float4 v = __ldg((const float4*)(W + k * 128 + n4));
        float vals[4] = {v.x, v.y, v.z, v.w};
#pragma unroll
        for (int j = 0; j < 4; ++j) {
            int n = n4 + j;
            int cp = (n & ~31) | ((n & 7) << 2) | ((n >> 3) & 3);
            *(uint32_t*)(Bs + k * LDB + cp) = to_tf32(vals[j]);
        }
    }
}

// warp-tile GEMM: acc += A[32-row strip] * B[32-col strip], K=128
__device__ __forceinline__ void mma_tile32(const float* __restrict__ As,
                                           const float* __restrict__ Bs,
                                           float (&acc)[2][4][4],
                                           int lane, int warpM, int wc) {
    const int g = lane >> 2, tig = lane & 3;
#pragma unroll
    for (int ks = 0; ks < 16; ++ks) {
        const int k0 = ks * 8;
        uint32_t a[2][4];
#pragma unroll
        for (int mi = 0; mi < 2; ++mi) {
            const float* Ap = As + (warpM + mi * 16 + g) * LDA + k0 + tig;
            a[mi][0] = to_tf32(Ap[0]);
            a[mi][1] = to_tf32(Ap[8 * LDA]);
            a[mi][2] = to_tf32(Ap[4]);
            a[mi][3] = to_tf32(Ap[8 * LDA + 4]);
        }
        float4 b0 = *(const float4*)(Bs + (k0 + tig) * LDB + wc * 32 + (g << 2));
        float4 b1 = *(const float4*)(Bs + (k0 + tig + 4) * LDB + wc * 32 + (g << 2));
        uint32_t bA[4] = {__float_as_uint(b0.x), __float_as_uint(b0.y),
                          __float_as_uint(b0.z), __float_as_uint(b0.w)};
        uint32_t bB[4] = {__float_as_uint(b1.x), __float_as_uint(b1.y),
                          __float_as_uint(b1.z), __float_as_uint(b1.w)};
#pragma unroll
        for (int mi = 0; mi < 2; ++mi)
#pragma unroll
            for (int ni = 0; ni < 4; ++ni)
                asm volatile(
                    "mma.sync.aligned.m16n8k8.row.col.f32.tf32.tf32.f32 "
                    "{%0,%1,%2,%3}, {%4,%5,%6,%7}, {%8,%9}, {%0,%1,%2,%3};"
                    : "+f"(acc[mi][ni][0]), "+f"(acc[mi][ni][1]),
                      "+f"(acc[mi][ni][2]), "+f"(acc[mi][ni][3])
                    : "r"(a[mi][0]), "r"(a[mi][1]), "r"(a[mi][2]), "r"(a[mi][3]),
                      "r"(bA[ni]), "r"(bB[ni]));
    }
}

// dual-B variant (pkern)
__device__ __forceinline__ void mma_tile32_dual(const float* __restrict__ As,
                                                const float* __restrict__ B0s,
                                                const float* __restrict__ B1s,
                                                float (&acc1)[2][4][4], float (&acc2)[2][4][4],
                                                int lane, int warpM, int wc) {
    const int g = lane >> 2, tig = lane & 3;
#pragma unroll
    for (int ks = 0; ks < 16; ++ks) {
        const int k0 = ks * 8;
        uint32_t a[2][4];
#pragma unroll
        for (int mi = 0; mi < 2; ++mi) {
            const float* Ap = As + (warpM + mi * 16 + g) * LDA + k0 + tig;
            a[mi][0] = to_tf32(Ap[0]);
            a[mi][1] = to_tf32(Ap[8 * LDA]);
            a[mi][2] = to_tf32(Ap[4]);
            a[mi][3] = to_tf32(Ap[8 * LDA + 4]);
        }
#pragma unroll
        for (int which = 0; which < 2; ++which) {
            const float* Bs = which ? B1s : B0s;
            float4 b0 = *(const float4*)(Bs + (k0 + tig) * LDB + wc * 32 + (g << 2));
            float4 b1 = *(const float4*)(Bs + (k0 + tig + 4) * LDB + wc * 32 + (g << 2));
            uint32_t bA[4] = {__float_as_uint(b0.x), __float_as_uint(b0.y),
                              __float_as_uint(b0.z), __float_as_uint(b0.w)};
            uint32_t bB[4] = {__float_as_uint(b1.x), __float_as_uint(b1.y),
                              __float_as_uint(b1.z), __float_as_uint(b1.w)};
            float (&acc)[2][4][4] = which ? acc2 : acc1;
#pragma unroll
            for (int mi = 0; mi < 2; ++mi)
#pragma unroll
                for (int ni = 0; ni < 4; ++ni)
                    asm volatile(
                        "mma.sync.aligned.m16n8k8.row.col.f32.tf32.tf32.f32 "
                        "{%0,%1,%2,%3}, {%4,%5,%6,%7}, {%8,%9}, {%0,%1,%2,%3};"
                        : "+f"(acc[mi][ni][0]), "+f"(acc[mi][ni][1]),
                          "+f"(acc[mi][ni][2]), "+f"(acc[mi][ni][3])
                        : "r"(a[mi][0]), "r"(a[mi][1]), "r"(a[mi][2]), "r"(a[mi][3]),
                          "r"(bA[ni]), "r"(bB[ni]));
        }
    }
}

__device__ __forceinline__ void zero_acc32(float (&acc)[2][4][4]) {
#pragma unroll
    for (int i = 0; i < 2; ++i)
#pragma unroll
        for (int j = 0; j < 4; ++j)
#pragma unroll
            for (int q = 0; q < 4; ++q) acc[i][j][q] = 0.f;
}

// ---------------------------------------------------------------------------
// setup kernels
// ---------------------------------------------------------------------------
__global__ void zero_kern() {
    int t = blockIdx.x * blockDim.x + threadIdx.x;
    int stride = gridDim.x * blockDim.x;
    float4* a4 = (float4*)g_agg;
    for (int i = t; i < N_NODES * 32; i += stride) a4[i] = make_float4(0.f, 0.f, 0.f, 0.f);
    for (int i = t; i < N_NODES; i += stride) g_cnt[i] = 0;
}

__global__ void conv_kern(const void* __restrict__ p) {
    const long long* q = (const long long*)p;
    int bad = 0;
    for (int i = threadIdx.x; i < 2048; i += blockDim.x) {
        long long v = q[i];
        if (v < 0 || v >= N_NODES) bad = 1;
    }
    int is32 = __syncthreads_or(bad);

    int t = blockIdx.x * blockDim.x + threadIdx.x;
    int stride = gridDim.x * blockDim.x;
    if (is32) {
        const int* qi = (const int*)p;
        for (int e = t; e < N_EDGES; e += stride) {
            int r = qi[e];
            g_row[e] = r;
            g_col[e] = qi[N_EDGES + e];
            atomicAdd(&g_cnt[r], 1);
        }
    } else {
        for (int e = t; e < N_EDGES; e += stride) {
            int r = (int)q[e];
            g_row[e] = r;
            g_col[e] = (int)q[N_EDGES + e];
            atomicAdd(&g_cnt[r], 1);
        }
    }
}

// ---------------------------------------------------------------------------
// pkern: g_P = x @ [W_src | W_dst]  (fused dual-B k-loop; unchanged)
// ---------------------------------------------------------------------------
__global__ __launch_bounds__(512, 1) void pkern(const float* __restrict__ x,
                                                const float* __restrict__ We1) {
    extern __shared__ float sm[];
    float* A  = sm;
    float* B0 = sm + A_FLOATS;
    float* B1 = B0 + B_FLOATS;
    int tid = threadIdx.x, lane = tid & 31, wid = tid >> 5;
    int warpM = (wid >> 2) << 5, wc = wid & 3;
    int g = lane >> 2, tig = lane & 3;
    int nBase = blockIdx.x * 128;
    int valid = min(128, N_NODES - nBase);

    cpa_tile(A, x + (size_t)nBase * 128, tid, valid);
    CP_COMMIT();
    load_B_tf32(B0, We1, tid, 512);
    load_B_tf32(B1, We1 + 128 * 128, tid, 512);
    CP_WAIT_ALL();
    __syncthreads();

    float acc1[2][4][4], acc2[2][4][4];
    zero_acc32(acc1); zero_acc32(acc2);
    mma_tile32_dual(A, B0, B1, acc1, acc2, lane, warpM, wc);
    __syncthreads();

#pragma unroll
    for (int pass = 0; pass < 2; ++pass) {
        float (&acc)[2][4][4] = pass ? acc2 : acc1;
#pragma unroll
        for (int mi = 0; mi < 2; ++mi)
#pragma unroll
            for (int half = 0; half < 2; ++half) {
                int m = warpM + mi * 16 + g + half * 8;
#pragma unroll
                for (int ni = 0; ni < 4; ++ni) {
                    int c = wc * 32 + ni * 8 + 2 * tig;
                    *(float2*)(A + m * LDA + c) =
                        make_float2(acc[mi][ni][half * 2], acc[mi][ni][half * 2 + 1]);
                }
            }
        __syncthreads();
        int row = tid >> 2;
        int n = nBase + row;
        if (n < N_NODES) {
#pragma unroll
            for (int i = 0; i < 8; ++i) {
                int c = ((tid & 3) + i * 4) << 2;
                *(float4*)(g_P + (size_t)n * 256 + pass * 128 + c) = *(const float4*)(A + row * LDA + c);
            }
        }
        __syncthreads();
    }
}

// ---------------------------------------------------------------------------
// ekern v4: two independent 8-warp pipelines per CTA (named barriers),
// each on its own 64-edge tile stream; shared resident weights.
// ---------------------------------------------------------------------------
__global__ __launch_bounds__(512, 1) void ekern(const float* __restrict__ attr,
                                                const float* __restrict__ We1,
                                                const float* __restrict__ be1,
                                                const float* __restrict__ We2,
                                                const float* __restrict__ be2,
                                                float* __restrict__ edge_out) {
    extern __shared__ float sm[];
    // [A0: 64*LDA][A1: 64*LDA][B1][B2]
    float* B1 = sm + 2 * 64 * LDA;
    float* B2 = B1 + B_FLOATS;
    __shared__ int rows_s[2][2][64], cols_s[2][2][64];  // [grp][buf][row]
    __shared__ float be1s[128], be2s[128];

    int tid = threadIdx.x, lane = tid & 31, wid = tid >> 5;
    int grp  = wid >> 3;          // 0 or 1
    int gtid = tid & 255;
    int gwid = wid & 7;
    int warpM = (gwid >> 2) << 5; // 0 or 32
    int wc = gwid & 3;
    int g = lane >> 2, tig = lane & 3;
    const int cbase = wc * 32 + 2 * tig;
    float* A = sm + grp * 64 * LDA;

    load_B_tf32(B1, We1 + 2 * 128 * 128, tid, 512);  // W_e
    load_B_tf32(B2, We2, tid, 512);
    if (tid < 128) { be1s[tid] = be1[tid]; be2s[tid] = be2[tid]; }
    __syncthreads();

    const int NUM_T64 = N_EDGES / 64;     // 10000
    const int step = gridDim.x * 2;       // 296
    const int t0 = blockIdx.x * 2 + grp;

    // prologue: prefetch first tile for this group
    {
        int eB = t0 << 6;
#pragma unroll
        for (int i = 0; i < 8; ++i) {
            int idx = gtid + i * 256;
            int r = idx >> 5, c4 = (idx & 31) << 2;
            cp_async16(smem_u32(A + r * LDA + c4), attr + (size_t)eB * 128 + r * 128 + c4, 16);
        }
        if (gtid < 16)
            cp_async16(smem_u32(&rows_s[grp][0][gtid * 4]), g_row + eB + gtid * 4, 16);
        else if (gtid < 32)
            cp_async16(smem_u32(&cols_s[grp][0][(gtid - 16) * 4]), g_col + eB + (gtid - 16) * 4, 16);
        CP_COMMIT();
    }

    int buf = 0;
    for (int t = t0; t < NUM_T64; t += step) {
        int eB = t << 6;
        CP_WAIT_ALL();
        GBAR(grp);   // tile + indices visible to group

        // ---- P prefetch for mi=0 rows (hidden under GEMM1) ----
        int m0 = warpM + g, m1 = warpM + 8 + g;
        int r0 = rows_s[grp][buf][m0], c0i = cols_s[grp][buf][m0];
        int r1 = rows_s[grp][buf][m1], c1i = cols_s[grp][buf][m1];
        float2 ps0[2][4], pd0[2][4];
#pragma unroll
        for (int ni = 0; ni < 4; ++ni) {
            int c = cbase + ni * 8;
            ps0[0][ni] = *(const float2*)(g_P + (size_t)r0 * 256 + c);
            pd0[0][ni] = *(const float2*)(g_P + (size_t)c0i * 256 + 128 + c);
            ps0[1][ni] = *(const float2*)(g_P + (size_t)r1 * 256 + c);
            pd0[1][ni] = *(const float2*)(g_P + (size_t)c1i * 256 + 128 + c);
        }

        float acc1[2][4][4];
        zero_acc32(acc1);
        mma_tile32(A, B1, acc1, lane, warpM, wc);
        GBAR(grp);   // group done reading A

        // ---- epilogue 1: h = relu(D1 + Psrc + Pdst + be1) -> A ----
        {
            int m2 = warpM + 16 + g, m3 = warpM + 24 + g;
            int r2 = rows_s[grp][buf][m2], c2i = cols_s[grp][buf][m2];
            int r3 = rows_s[grp][buf][m3], c3i = cols_s[grp][buf][m3];
            float2 ps1[2][4], pd1[2][4];
#pragma unroll
            for (int ni = 0; ni < 4; ++ni) {
                int c = cbase + ni * 8;
                ps1[0][ni] = *(const float2*)(g_P + (size_t)r2 * 256 + c);
                pd1[0][ni] = *(const float2*)(g_P + (size_t)c2i * 256 + 128 + c);
                ps1[1][ni] = *(const float2*)(g_P + (size_t)r3 * 256 + c);
                pd1[1][ni] = *(const float2*)(g_P + (size_t)c3i * 256 + 128 + c);
            }
#pragma unroll
            for (int half = 0; half < 2; ++half) {
                int m = warpM + g + half * 8;
#pragma unroll
                for (int ni = 0; ni < 4; ++ni) {
                    int c = cbase + ni * 8;
                    float v0 = fmaxf(acc1[0][ni][half * 2]     + ps0[half][ni].x + pd0[half][ni].x + be1s[c],     0.f);
                    float v1 = fmaxf(acc1[0][ni][half * 2 + 1] + ps0[half][ni].y + pd0[half][ni].y + be1s[c + 1], 0.f);
                    *(float2*)(A + m * LDA + c) = make_float2(v0, v1);
                }
            }
#pragma unroll
            for (int half = 0; half < 2; ++half) {
                int m = warpM + 16 + g + half * 8;
#pragma unroll
                for (int ni = 0; ni < 4; ++ni) {
                    int c = cbase + ni * 8;
                    float v0 = fmaxf(acc1[1][ni][half * 2]     + ps1[half][ni].x + pd1[half][ni].x + be1s[c],     0.f);
                    float v1 = fmaxf(acc1[1][ni][half * 2 + 1] + ps1[half][ni].y + pd1[half][ni].y + be1s[c + 1], 0.f);
                    *(float2*)(A + m * LDA + c) = make_float2(v0, v1);
                }
            }
        }
        GBAR(grp);   // h visible

        float acc2[2][4][4];
        zero_acc32(acc2);
        mma_tile32(A, B2, acc2, lane, warpM, wc);
        GBAR(grp);   // group done reading A(h)

        // ---- stage D2 + be2 into A ----
#pragma unroll
        for (int mi = 0; mi < 2; ++mi)
#pragma unroll
            for (int half = 0; half < 2; ++half) {
                int m = warpM + mi * 16 + g + half * 8;
#pragma unroll
                for (int ni = 0; ni < 4; ++ni) {
                    int c = cbase + ni * 8;
                    *(float2*)(A + m * LDA + c) =
                        make_float2(acc2[mi][ni][half * 2]     + be2s[c],
                                    acc2[mi][ni][half * 2 + 1] + be2s[c + 1]);
                }
            }
        GBAR(grp);   // staged values visible

        // ---- read staged rows into regs (256 threads, 64 rows) ----
        int row = gtid >> 2;
        int rdst = rows_s[grp][buf][row];
        float4 v[8];
#pragma unroll
        for (int i = 0; i < 8; ++i) {
            int c = ((gtid & 3) + i * 4) << 2;
            v[i] = *(const float4*)(A + row * LDA + c);
        }
        GBAR(grp);   // staged reads done -> A reusable

        // ---- prefetch next tile (overlaps stores/atomics) ----
        int tn = t + step;
        if (tn < NUM_T64) {
            int eN = tn << 6;
#pragma unroll
            for (int i = 0; i < 8; ++i) {
                int idx = gtid + i * 256;
                int r = idx >> 5, c4 = (idx & 31) << 2;
                cp_async16(smem_u32(A + r * LDA + c4), attr + (size_t)eN * 128 + r * 128 + c4, 16);
            }
            if (gtid < 16)
                cp_async16(smem_u32(&rows_s[grp][buf ^ 1][gtid * 4]), g_row + eN + gtid * 4, 16);
            else if (gtid < 32)
                cp_async16(smem_u32(&cols_s[grp][buf ^ 1][(gtid - 16) * 4]), g_col + eN + (gtid - 16) * 4, 16);
        }
        CP_COMMIT();

        // ---- stores + atomics ----
        {
            float* eo = edge_out + (size_t)(eB + row) * 128;
            float* ag = g_agg + (size_t)rdst * 128;
#pragma unroll
            for (int i = 0; i < 8; ++i) {
                int c = ((gtid & 3) + i * 4) << 2;
                *(float4*)(eo + c) = v[i];
                atomicAdd((float4*)(ag + c), v[i]);
            }
        }
        buf ^= 1;
    }
}

// ---------------------------------------------------------------------------
// nkern (unchanged)
// ---------------------------------------------------------------------------
__global__ __launch_bounds__(512, 1) void nkern(const float* __restrict__ x,
                                                const float* __restrict__ Wn1,
                                                const float* __restrict__ bn1,
                                                const float* __restrict__ Wn2,
                                                const float* __restrict__ bn2,
                                                float* __restrict__ x_out) {
    extern __shared__ float sm[];
    float* A  = sm;
    float* B0 = sm + A_FLOATS;
    float* B1 = B0 + B_FLOATS;
    __shared__ float bn1s[128], bn2s[128], scale_s[128];

    int tid = threadIdx.x, lane = tid & 31, wid = tid >> 5;
    int warpM = (wid >> 2) << 5, wc = wid & 3;
    int g = lane >> 2, tig = lane & 3;
    int nBase = blockIdx.x * 128;
    int valid = min(128, N_NODES - nBase);

    cpa_tile(A, x + (size_t)nBase * 128, tid, valid);
    CP_COMMIT();
    load_B_tf32(B0, Wn1, tid, 512);
    load_B_tf32(B1, Wn1 + 128 * 128, tid, 512);
    if (tid < 128) {
        bn1s[tid] = bn1[tid];
        bn2s[tid] = bn2[tid];
        int n = nBase + tid;
        float c = (n < N_NODES) ? (float)g_cnt[n] : 1.f;
        scale_s[tid] = 1.f / fmaxf(c, 1.f);
    }
    CP_WAIT_ALL();
    __syncthreads();

    float acc[2][4][4];
    zero_acc32(acc);
    mma_tile32(A, B0, acc, lane, warpM, wc);
    __syncthreads();

    for (int i = tid; i < 4096; i += 512) {
        int r = i >> 5, c4 = (i & 31) << 2;
        int n = nBase + r;
        float4 v = make_float4(0.f, 0.f, 0.f, 0.f);
        if (n < N_NODES) {
            v = *(const float4*)(g_agg + (size_t)n * 128 + c4);
            float s = scale_s[r];
            v.x *= s; v.y *= s; v.z *= s; v.w *= s;
        }
        *(float4*)(A + r * LDA + c4) = v;
    }
    __syncthreads();
    mma_tile32(A, B1, acc, lane, warpM, wc);
    __syncthreads();

#pragma unroll
    for (int mi = 0; mi < 2; ++mi)
#pragma unroll
        for (int half = 0; half < 2; ++half) {
            int m = warpM + mi * 16 + g + half * 8;
#pragma unroll
            for (int ni = 0; ni < 4; ++ni) {
                int c = wc * 32 + ni * 8 + 2 * tig;
                float v0 = fmaxf(acc[mi][ni][half * 2]     + bn1s[c],     0.f);
                float v1 = fmaxf(acc[mi][ni][half * 2 + 1] + bn1s[c + 1], 0.f);
                *(float2*)(A + m * LDA + c) = make_float2(v0, v1);
            }
        }
    load_B_tf32(B0, Wn2, tid, 512);
    __syncthreads();

    float acc2[2][4][4];
    zero_acc32(acc2);
    mma_tile32(A, B0, acc2, lane, warpM, wc);
    __syncthreads();

#pragma unroll
    for (int mi = 0; mi < 2; ++mi)
#pragma unroll
        for (int half = 0; half < 2; ++half) {
            int m = warpM + mi * 16 + g + half * 8;
#pragma unroll
            for (int ni = 0; ni < 4; ++ni) {
                int c = wc * 32 + ni * 8 + 2 * tig;
                *(float2*)(A + m * LDA + c) =
                    make_float2(acc2[mi][ni][half * 2]     + bn2s[c],
                                acc2[mi][ni][half * 2 + 1] + bn2s[c + 1]);
            }
        }
    __syncthreads();
    {
        int row = tid >> 2;
        int n = nBase + row;
        if (n < N_NODES) {
#pragma unroll
            for (int i = 0; i < 8; ++i) {
                int c = ((tid & 3) + i * 4) << 2;
                *(float4*)(x_out + (size_t)n * 128 + c) = *(const float4*)(A + row * LDA + c);
            }
        }
    }
}

// ---------------------------------------------------------------------------
extern "C" void kernel_launch(void* const* d_in, const int* in_sizes, int n_in,
                              void* d_out, int out_size) {
    const float* x    = (const float*)d_in[0];
    const void*  eidx = d_in[1];
    const float* attr = (const float*)d_in[2];
    const float* We1  = (const float*)d_in[3];
    const float* be1  = (const float*)d_in[4];
    const float* We2  = (const float*)d_in[5];
    const float* be2  = (const float*)d_in[6];
    const float* Wn1  = (const float*)d_in[7];
    const float* bn1  = (const float*)d_in[8];
    const float* Wn2  = (const float*)d_in[9];
    const float* bn2  = (const float*)d_in[10];

    float* out      = (float*)d_out;
    float* x_out    = out;                          // [N, 128]
    float* edge_out = out + (size_t)N_NODES * 128;  // [E, 128]

    cudaFuncSetAttribute(pkern, cudaFuncAttributeMaxDynamicSharedMemorySize, SMEM_BYTES);
    cudaFuncSetAttribute(ekern, cudaFuncAttributeMaxDynamicSharedMemorySize, SMEM_BYTES);
    cudaFuncSetAttribute(nkern, cudaFuncAttributeMaxDynamicSharedMemorySize, SMEM_BYTES);

    zero_kern<<<640, 256>>>();
    conv_kern<<<640, 256>>>(eidx);
    pkern<<<(N_NODES + 127) / 128, 512, SMEM_BYTES>>>(x, We1);
    ekern<<<148, 512, SMEM_BYTES>>>(attr, We1, be1, We2, be2, edge_out);
    nkern<<<(N_NODES + 127) / 128, 512, SMEM_BYTES>>>(x, Wn1, bn1, Wn2, bn2, x_out);
}